// round 1
// baseline (speedup 1.0000x reference)
#include <cuda_runtime.h>

#define NN   50000
#define NE   800000
#define DIN  128
#define DH   256
#define NG   256
#define DH2  128

// ---------------- scratch (device globals; no allocations allowed) ----------
__device__ float g_agg1[(size_t)NN * DIN];
__device__ float g_h1  [(size_t)NN * DH];
__device__ float g_agg2[(size_t)NN * DH];
__device__ float g_h2  [(size_t)NN * DH];
__device__ int   g_deg [NN];
__device__ int   g_rowptr[NN + 1];
__device__ int   g_pos [NN];
__device__ int   g_esrc[NE];
__device__ float g_hg  [NG * DH];

// ---------------- CSR build -------------------------------------------------
__global__ void k_zero_deg() {
    int i = blockIdx.x * blockDim.x + threadIdx.x;
    if (i < NN) g_deg[i] = 0;
}

__global__ void k_hist(const int* __restrict__ dst) {
    int e = blockIdx.x * blockDim.x + threadIdx.x;
    if (e < NE) atomicAdd(&g_deg[dst[e]], 1);
}

// single-block exclusive scan over g_deg -> g_rowptr, also seeds g_pos
__global__ void k_scan() {
    __shared__ int sh[1024];
    __shared__ int carry;
    if (threadIdx.x == 0) carry = 0;
    __syncthreads();
    for (int base = 0; base < NN; base += 1024) {
        int i = base + threadIdx.x;
        int v = (i < NN) ? g_deg[i] : 0;
        sh[threadIdx.x] = v;
        __syncthreads();
        // Hillis-Steele inclusive scan
        for (int off = 1; off < 1024; off <<= 1) {
            int t = (threadIdx.x >= off) ? sh[threadIdx.x - off] : 0;
            __syncthreads();
            sh[threadIdx.x] += t;
            __syncthreads();
        }
        int incl = sh[threadIdx.x];
        int excl = incl - v + carry;
        if (i < NN) { g_rowptr[i] = excl; g_pos[i] = excl; }
        __syncthreads();
        if (threadIdx.x == 1023) carry += sh[1023];
        __syncthreads();
    }
    if (threadIdx.x == 0) g_rowptr[NN] = carry;
}

__global__ void k_scatter(const int* __restrict__ src, const int* __restrict__ dst) {
    int e = blockIdx.x * blockDim.x + threadIdx.x;
    if (e < NE) {
        int p = atomicAdd(&g_pos[dst[e]], 1);
        g_esrc[p] = src[e];
    }
}

// ---------------- mean aggregation (gather-sum over CSR) --------------------
template <int F>
__global__ void k_agg(const float* __restrict__ hin, float* __restrict__ hout) {
    int node = blockIdx.x;
    int f    = threadIdx.x;
    int beg  = g_rowptr[node];
    int end  = g_rowptr[node + 1];
    float acc = 0.f;
    for (int e = beg; e < end; ++e) {
        int s = g_esrc[e];
        acc += __ldg(&hin[(size_t)s * F + f]);
    }
    int d = end - beg;
    float inv = (d > 0) ? (1.f / (float)d) : 0.f;
    hout[(size_t)node * F + f] = acc * inv;
}

// ---------------- tiled fp32 GEMM: C = relu?(A@B + bias) --------------------
#define BM 128
#define BN 64
#define BK 16
#define TM 8
#define TN 4

__global__ __launch_bounds__(256) void k_gemm_bias_relu(
    const float* __restrict__ A, const float* __restrict__ B,
    const float* __restrict__ bias, float* __restrict__ C,
    int M, int N, int K, int do_relu)
{
    __shared__ float As[BK][BM + 4];
    __shared__ float Bs[BK][BN + 4];
    int tid  = threadIdx.x;
    int tcol = tid & 15;   // BN/TN = 16
    int trow = tid >> 4;   // BM/TM = 16
    int m0 = blockIdx.x * BM;
    int n0 = blockIdx.y * BN;

    float acc[TM][TN];
#pragma unroll
    for (int i = 0; i < TM; i++)
#pragma unroll
        for (int j = 0; j < TN; j++) acc[i][j] = 0.f;

    for (int k0 = 0; k0 < K; k0 += BK) {
#pragma unroll
        for (int t = 0; t < (BM * BK) / 256; ++t) {     // 8 per thread
            int idx = t * 256 + tid;
            int r = idx >> 4;
            int c = idx & 15;
            int gr = m0 + r;
            As[c][r] = (gr < M) ? A[(size_t)gr * K + k0 + c] : 0.f;
        }
#pragma unroll
        for (int t = 0; t < (BK * BN) / 256; ++t) {     // 4 per thread
            int idx = t * 256 + tid;
            int c = idx >> 6;
            int j = idx & 63;
            Bs[c][j] = B[(size_t)(k0 + c) * N + n0 + j];
        }
        __syncthreads();
#pragma unroll
        for (int kk = 0; kk < BK; ++kk) {
            float a[TM], b[TN];
#pragma unroll
            for (int i = 0; i < TM; i++) a[i] = As[kk][trow * TM + i];
#pragma unroll
            for (int j = 0; j < TN; j++) b[j] = Bs[kk][tcol * TN + j];
#pragma unroll
            for (int i = 0; i < TM; i++)
#pragma unroll
                for (int j = 0; j < TN; j++)
                    acc[i][j] += a[i] * b[j];
        }
        __syncthreads();
    }

#pragma unroll
    for (int i = 0; i < TM; i++) {
        int gr = m0 + trow * TM + i;
        if (gr < M) {
#pragma unroll
            for (int j = 0; j < TN; j++) {
                int gc = n0 + tcol * TN + j;
                float v = acc[i][j] + bias[gc];
                if (do_relu) v = fmaxf(v, 0.f);
                C[(size_t)gr * N + gc] = v;
            }
        }
    }
}

// ---------------- per-graph mean readout (graph_ids sorted) -----------------
__global__ void k_readout(const int* __restrict__ gids) {
    int g = blockIdx.x;           // 0..NG-1
    __shared__ int sb, se;
    if (threadIdx.x == 0) {
        int lo = 0, hi = NN;
        while (lo < hi) { int mid = (lo + hi) >> 1; if (gids[mid] < g) lo = mid + 1; else hi = mid; }
        sb = lo;
        lo = 0; hi = NN;
        while (lo < hi) { int mid = (lo + hi) >> 1; if (gids[mid] < g + 1) lo = mid + 1; else hi = mid; }
        se = lo;
    }
    __syncthreads();
    int beg = sb, end = se;
    int f = threadIdx.x;          // DH threads
    float acc = 0.f;
    for (int n = beg; n < end; ++n) acc += g_h2[(size_t)n * DH + f];
    float cnt = (float)(end - beg);
    g_hg[g * DH + f] = acc / fmaxf(cnt, 1.f);
}

// ---------------- final MLP: out[g] = (hg@Wr1+br1)@Wr2 + br2 ---------------
__global__ void k_mlp(const float* __restrict__ Wr1, const float* __restrict__ br1,
                      const float* __restrict__ Wr2, const float* __restrict__ br2,
                      float* __restrict__ out)
{
    int g = blockIdx.x;
    int j = threadIdx.x;          // DH2 = 128 threads
    __shared__ float shg[DH];
    shg[j]       = g_hg[g * DH + j];
    shg[j + 128] = g_hg[g * DH + j + 128];
    __syncthreads();
    float acc = br1[j];
#pragma unroll 4
    for (int k = 0; k < DH; ++k) acc += shg[k] * Wr1[k * DH2 + j];
    float v = acc * Wr2[j];
#pragma unroll
    for (int off = 16; off > 0; off >>= 1) v += __shfl_down_sync(0xffffffffu, v, off);
    __shared__ float ws[4];
    if ((j & 31) == 0) ws[j >> 5] = v;
    __syncthreads();
    if (j == 0) out[g] = ws[0] + ws[1] + ws[2] + ws[3] + br2[0];
}

// ---------------- launch ----------------------------------------------------
extern "C" void kernel_launch(void* const* d_in, const int* in_sizes, int n_in,
                              void* d_out, int out_size)
{
    const float* h    = (const float*)d_in[0];
    const int*   src  = (const int*)  d_in[1];
    const int*   dst  = (const int*)  d_in[2];
    const int*   gids = (const int*)  d_in[3];
    const float* W1   = (const float*)d_in[4];
    const float* b1   = (const float*)d_in[5];
    const float* W2   = (const float*)d_in[6];
    const float* b2   = (const float*)d_in[7];
    const float* Wr1  = (const float*)d_in[8];
    const float* br1  = (const float*)d_in[9];
    const float* Wr2  = (const float*)d_in[10];
    const float* br2  = (const float*)d_in[11];
    float* out = (float*)d_out;

    float *agg1, *h1, *agg2, *h2;
    cudaGetSymbolAddress((void**)&agg1, g_agg1);
    cudaGetSymbolAddress((void**)&h1,   g_h1);
    cudaGetSymbolAddress((void**)&agg2, g_agg2);
    cudaGetSymbolAddress((void**)&h2,   g_h2);

    // CSR build
    k_zero_deg<<<(NN + 255) / 256, 256>>>();
    k_hist<<<(NE + 255) / 256, 256>>>(dst);
    k_scan<<<1, 1024>>>();
    k_scatter<<<(NE + 255) / 256, 256>>>(src, dst);

    // layer 1
    k_agg<DIN><<<NN, DIN>>>(h, agg1);
    {
        dim3 grid((NN + BM - 1) / BM, DH / BN);
        k_gemm_bias_relu<<<grid, 256>>>(agg1, W1, b1, h1, NN, DH, DIN, 1);
    }
    // layer 2
    k_agg<DH><<<NN, DH>>>(h1, agg2);
    {
        dim3 grid((NN + BM - 1) / BM, DH / BN);
        k_gemm_bias_relu<<<grid, 256>>>(agg2, W2, b2, h2, NN, DH, DH, 1);
    }
    // readout + MLP
    k_readout<<<NG, DH>>>(gids);
    k_mlp<<<NG, DH2>>>(Wr1, br1, Wr2, br2, out);
}

// round 3
// speedup vs baseline: 1.6831x; 1.6831x over previous
#include <cuda_runtime.h>
#include <cuda_bf16.h>
#include <cstdint>

#define NN   50000
#define NE   800000
#define DIN  128
#define DH   256
#define NG   256
#define DH2  128

// ---------------- scratch (device globals; no allocations allowed) ----------
__device__ float         g_h1 [(size_t)NN * DH];
__device__ float         g_h2 [(size_t)NN * DH];
__device__ __nv_bfloat16 g_ahi[(size_t)NN * DH];
__device__ __nv_bfloat16 g_alo[(size_t)NN * DH];
__device__ __nv_bfloat16 g_whi[DH * DH];
__device__ __nv_bfloat16 g_wlo[DH * DH];
__device__ int   g_deg [NN];
__device__ int   g_rowptr[NN + 1];
__device__ int   g_pos [NN];
__device__ int   g_esrc[NE];
__device__ float g_hg  [NG * DH];

// ---------------- helpers ---------------------------------------------------
__device__ __forceinline__ uint32_t smem_u32(const void* p) {
    uint32_t a;
    asm("{ .reg .u64 t; cvta.to.shared.u64 t, %1; cvt.u32.u64 %0, t; }"
        : "=r"(a) : "l"(p));
    return a;
}

__device__ __forceinline__ void ldm_x4(uint32_t* f, uint32_t sa) {
    asm volatile("ldmatrix.sync.aligned.m8n8.x4.shared.b16 {%0,%1,%2,%3}, [%4];"
                 : "=r"(f[0]), "=r"(f[1]), "=r"(f[2]), "=r"(f[3]) : "r"(sa));
}

__device__ __forceinline__ void mma16816(float* c, const uint32_t* a, const uint32_t* b) {
    asm volatile(
        "mma.sync.aligned.m16n8k16.row.col.f32.bf16.bf16.f32 "
        "{%0,%1,%2,%3}, {%4,%5,%6,%7}, {%8,%9}, {%0,%1,%2,%3};"
        : "+f"(c[0]), "+f"(c[1]), "+f"(c[2]), "+f"(c[3])
        : "r"(a[0]), "r"(a[1]), "r"(a[2]), "r"(a[3]), "r"(b[0]), "r"(b[1]));
}

// ---------------- CSR build -------------------------------------------------
__global__ void k_zero_deg() {
    int i = blockIdx.x * blockDim.x + threadIdx.x;
    if (i < NN) g_deg[i] = 0;
}

__global__ void k_hist(const int* __restrict__ dst) {
    int e = blockIdx.x * blockDim.x + threadIdx.x;
    if (e < NE) atomicAdd(&g_deg[dst[e]], 1);
}

// chunked single-block scan: 1024 threads * 49 elems
__global__ void k_scan() {
    const int CH = 49;
    int t = threadIdx.x;
    int beg = t * CH;
    int end = beg + CH; if (end > NN) end = NN;
    int s = 0;
    for (int i = beg; i < end; ++i) s += g_deg[i];
    int lane = t & 31, w = t >> 5;
    int v = s;
#pragma unroll
    for (int o = 1; o < 32; o <<= 1) {
        int u = __shfl_up_sync(0xffffffffu, v, o);
        if (lane >= o) v += u;
    }
    __shared__ int wsum[32];
    if (lane == 31) wsum[w] = v;
    __syncthreads();
    if (w == 0) {
        int x = wsum[lane];
#pragma unroll
        for (int o = 1; o < 32; o <<= 1) {
            int u = __shfl_up_sync(0xffffffffu, x, o);
            if (lane >= o) x += u;
        }
        wsum[lane] = x;
    }
    __syncthreads();
    int excl = v - s + (w > 0 ? wsum[w - 1] : 0);
    for (int i = beg; i < end; ++i) {
        int d = g_deg[i];
        g_rowptr[i] = excl;
        g_pos[i]    = excl;
        excl += d;
    }
    if (t == 1023) g_rowptr[NN] = wsum[31];
}

__global__ void k_scatter(const int* __restrict__ src, const int* __restrict__ dst) {
    int e = blockIdx.x * blockDim.x + threadIdx.x;
    if (e < NE) {
        int p = atomicAdd(&g_pos[dst[e]], 1);
        g_esrc[p] = src[e];
    }
}

// ------------- mean aggregation + bf16 hi/lo split (float4 lanes) -----------
template <int F>
__global__ void k_agg_split(const float* __restrict__ hin,
                            __nv_bfloat16* __restrict__ hi,
                            __nv_bfloat16* __restrict__ lo) {
    int node = blockIdx.x;
    int f4   = threadIdx.x;              // F/4 threads, 4 floats each
    int beg  = g_rowptr[node];
    int end  = g_rowptr[node + 1];
    float4 acc = make_float4(0.f, 0.f, 0.f, 0.f);
    int e = beg;
    for (; e + 1 < end; e += 2) {
        int s0 = g_esrc[e], s1 = g_esrc[e + 1];
        float4 v0 = __ldg((const float4*)(hin + (size_t)s0 * F) + f4);
        float4 v1 = __ldg((const float4*)(hin + (size_t)s1 * F) + f4);
        acc.x += v0.x + v1.x; acc.y += v0.y + v1.y;
        acc.z += v0.z + v1.z; acc.w += v0.w + v1.w;
    }
    if (e < end) {
        float4 v0 = __ldg((const float4*)(hin + (size_t)g_esrc[e] * F) + f4);
        acc.x += v0.x; acc.y += v0.y; acc.z += v0.z; acc.w += v0.w;
    }
    float inv = (end > beg) ? (1.f / (float)(end - beg)) : 0.f;
    float m[4] = { acc.x * inv, acc.y * inv, acc.z * inv, acc.w * inv };
    __nv_bfloat16 hv[4], lv[4];
#pragma unroll
    for (int j = 0; j < 4; ++j) {
        hv[j] = __float2bfloat16(m[j]);
        lv[j] = __float2bfloat16(m[j] - __bfloat162float(hv[j]));
    }
    *(uint2*)(hi + (size_t)node * F + 4 * f4) = *(uint2*)hv;
    *(uint2*)(lo + (size_t)node * F + 4 * f4) = *(uint2*)lv;
}

// -------- weight transpose + split: Wt[n][k] = W[k][n], bf16 hi/lo ----------
__global__ void k_prep_w(const float* __restrict__ W, int K,
                         __nv_bfloat16* __restrict__ hi,
                         __nv_bfloat16* __restrict__ lo) {
    int idx = blockIdx.x * blockDim.x + threadIdx.x;
    if (idx < DH * K) {
        int n = idx / K, k = idx % K;
        float v = W[(size_t)k * DH + n];
        __nv_bfloat16 h = __float2bfloat16(v);
        hi[idx] = h;
        lo[idx] = __float2bfloat16(v - __bfloat162float(h));
    }
}

// ---------------- HMMA GEMM: C = relu(A @ Wt^T + bias) ----------------------
// A: [NN x K] bf16 hi/lo row-major; Wt: [256 x K] bf16 hi/lo (n-major, K contig)
// C: [NN x 256] f32. BM=128, BN=128, BK=32; 8 warps as 4(M) x 2(N), warp 32x64.
#define LDA 40   // 32 + 8 pad (bf16 units); row stride 80 B (16B-aligned)

template <int K>
__global__ __launch_bounds__(256) void k_gemm_hmma(
    const __nv_bfloat16* __restrict__ Ahi, const __nv_bfloat16* __restrict__ Alo,
    const __nv_bfloat16* __restrict__ Bhi, const __nv_bfloat16* __restrict__ Blo,
    const float* __restrict__ bias, float* __restrict__ C)
{
    __shared__ __nv_bfloat16 sAhi[128 * LDA];
    __shared__ __nv_bfloat16 sAlo[128 * LDA];
    __shared__ __nv_bfloat16 sBhi[128 * LDA];
    __shared__ __nv_bfloat16 sBlo[128 * LDA];

    const int tid  = threadIdx.x;
    const int lane = tid & 31;
    const int wid  = tid >> 5;
    const int wm   = (wid >> 1) * 32;     // warp M offset in tile
    const int wn   = (wid & 1) * 64;      // warp N offset in tile
    const int m0   = blockIdx.x * 128;
    const int n0   = blockIdx.y * 128;

    float c[2][8][4];
#pragma unroll
    for (int i = 0; i < 2; ++i)
#pragma unroll
        for (int j = 0; j < 8; ++j)
#pragma unroll
            for (int q = 0; q < 4; ++q) c[i][j][q] = 0.f;

    // ldmatrix per-lane smem byte offsets (ks=0; ks=1 adds 32 bytes)
    // A frag (16x16): q=lane>>3: {rows0-7,k0},{rows8-15,k0},{rows0-7,k8},{rows8-15,k8}
    const int aq = lane >> 3, ar = lane & 7;
    const int a_row = ar + (aq & 1) * 8;
    const int a_col = (aq >> 1) * 8;
    uint32_t aoff[2];
#pragma unroll
    for (int i = 0; i < 2; ++i)
        aoff[i] = (uint32_t)(((wm + i * 16 + a_row) * LDA + a_col) * 2);
    // B frag pair (two n8 tiles): q: {tile j,k0},{tile j,k8},{tile j+1,k0},{tile j+1,k8}
    const int b_row = (aq >> 1) * 8 + ar;
    const int b_col = (aq & 1) * 8;
    uint32_t boff[4];
#pragma unroll
    for (int jp = 0; jp < 4; ++jp)
        boff[jp] = (uint32_t)(((wn + jp * 16 + b_row) * LDA + b_col) * 2);

    const uint32_t sa_hi = smem_u32(sAhi), sa_lo = smem_u32(sAlo);
    const uint32_t sb_hi = smem_u32(sBhi), sb_lo = smem_u32(sBlo);

    for (int k0 = 0; k0 < K; k0 += 32) {
        // load tiles: 128 rows x 32 cols bf16 each; 512 uint4 per tile
#pragma unroll
        for (int t = 0; t < 2; ++t) {
            int idx = t * 256 + tid;        // 0..511
            int r = idx >> 2;               // row
            int cB = (idx & 3) * 8;         // col (bf16)
            uint32_t so = (uint32_t)((r * LDA + cB) * 2);
            int gr = m0 + r;
            uint4 vh = make_uint4(0, 0, 0, 0), vl = make_uint4(0, 0, 0, 0);
            if (gr < NN) {
                size_t off = (size_t)gr * K + k0 + cB;
                vh = *(const uint4*)(Ahi + off);
                vl = *(const uint4*)(Alo + off);
            }
            *(uint4*)((char*)sAhi + so) = vh;
            *(uint4*)((char*)sAlo + so) = vl;
            size_t boffg = (size_t)(n0 + r) * K + k0 + cB;
            *(uint4*)((char*)sBhi + so) = *(const uint4*)(Bhi + boffg);
            *(uint4*)((char*)sBlo + so) = *(const uint4*)(Blo + boffg);
        }
        __syncthreads();

#pragma unroll
        for (int ks = 0; ks < 2; ++ks) {
            uint32_t ahi[2][4], alo[2][4];
#pragma unroll
            for (int i = 0; i < 2; ++i) {
                ldm_x4(ahi[i], sa_hi + aoff[i] + ks * 32);
                ldm_x4(alo[i], sa_lo + aoff[i] + ks * 32);
            }
#pragma unroll
            for (int jp = 0; jp < 4; ++jp) {
                uint32_t bhi[4], blo[4];
                ldm_x4(bhi, sb_hi + boff[jp] + ks * 32);
                ldm_x4(blo, sb_lo + boff[jp] + ks * 32);
#pragma unroll
                for (int i = 0; i < 2; ++i) {
#pragma unroll
                    for (int jj = 0; jj < 2; ++jj) {
                        float* cc = c[i][jp * 2 + jj];
                        mma16816(cc, ahi[i], bhi + jj * 2);  // hi*hi
                        mma16816(cc, ahi[i], blo + jj * 2);  // hi*lo
                        mma16816(cc, alo[i], bhi + jj * 2);  // lo*hi
                    }
                }
            }
        }
        __syncthreads();
    }

    // epilogue: bias + relu, f32 store
    const int g   = lane >> 2;
    const int tig = lane & 3;
#pragma unroll
    for (int i = 0; i < 2; ++i) {
#pragma unroll
        for (int j = 0; j < 8; ++j) {
            int col  = n0 + wn + j * 8 + 2 * tig;
            float b0 = bias[col], b1 = bias[col + 1];
            int r0 = m0 + wm + i * 16 + g;
            if (r0 < NN) {
                float2 o;
                o.x = fmaxf(c[i][j][0] + b0, 0.f);
                o.y = fmaxf(c[i][j][1] + b1, 0.f);
                *(float2*)(C + (size_t)r0 * 256 + col) = o;
            }
            int r1 = r0 + 8;
            if (r1 < NN) {
                float2 o;
                o.x = fmaxf(c[i][j][2] + b0, 0.f);
                o.y = fmaxf(c[i][j][3] + b1, 0.f);
                *(float2*)(C + (size_t)r1 * 256 + col) = o;
            }
        }
    }
}

// ---------------- per-graph mean readout (graph_ids sorted) -----------------
__global__ void k_readout(const int* __restrict__ gids) {
    int g = blockIdx.x;
    __shared__ int sb_, se_;
    if (threadIdx.x == 0) {
        int lo = 0, hi = NN;
        while (lo < hi) { int mid = (lo + hi) >> 1; if (gids[mid] < g) lo = mid + 1; else hi = mid; }
        sb_ = lo;
        lo = 0; hi = NN;
        while (lo < hi) { int mid = (lo + hi) >> 1; if (gids[mid] < g + 1) lo = mid + 1; else hi = mid; }
        se_ = lo;
    }
    __syncthreads();
    int beg = sb_, end = se_;
    int f = threadIdx.x;
    float acc = 0.f;
    for (int n = beg; n < end; ++n) acc += g_h2[(size_t)n * DH + f];
    float cnt = (float)(end - beg);
    g_hg[g * DH + f] = acc / fmaxf(cnt, 1.f);
}

// ---------------- final MLP: out[g] = (hg@Wr1+br1)@Wr2 + br2 ---------------
__global__ void k_mlp(const float* __restrict__ Wr1, const float* __restrict__ br1,
                      const float* __restrict__ Wr2, const float* __restrict__ br2,
                      float* __restrict__ out) {
    int g = blockIdx.x;
    int j = threadIdx.x;
    __shared__ float shg[DH];
    shg[j]       = g_hg[g * DH + j];
    shg[j + 128] = g_hg[g * DH + j + 128];
    __syncthreads();
    float acc = br1[j];
#pragma unroll 4
    for (int k = 0; k < DH; ++k) acc += shg[k] * Wr1[k * DH2 + j];
    float v = acc * Wr2[j];
#pragma unroll
    for (int off = 16; off > 0; off >>= 1) v += __shfl_down_sync(0xffffffffu, v, off);
    __shared__ float ws[4];
    if ((j & 31) == 0) ws[j >> 5] = v;
    __syncthreads();
    if (j == 0) out[g] = ws[0] + ws[1] + ws[2] + ws[3] + br2[0];
}

// ---------------- launch ----------------------------------------------------
extern "C" void kernel_launch(void* const* d_in, const int* in_sizes, int n_in,
                              void* d_out, int out_size) {
    const float* h    = (const float*)d_in[0];
    const int*   src  = (const int*)  d_in[1];
    const int*   dst  = (const int*)  d_in[2];
    const int*   gids = (const int*)  d_in[3];
    const float* W1   = (const float*)d_in[4];
    const float* b1   = (const float*)d_in[5];
    const float* W2   = (const float*)d_in[6];
    const float* b2   = (const float*)d_in[7];
    const float* Wr1  = (const float*)d_in[8];
    const float* br1  = (const float*)d_in[9];
    const float* Wr2  = (const float*)d_in[10];
    const float* br2  = (const float*)d_in[11];
    float* out = (float*)d_out;

    float *h1, *h2;
    __nv_bfloat16 *ahi, *alo, *whi, *wlo;
    cudaGetSymbolAddress((void**)&h1,  g_h1);
    cudaGetSymbolAddress((void**)&h2,  g_h2);
    cudaGetSymbolAddress((void**)&ahi, g_ahi);
    cudaGetSymbolAddress((void**)&alo, g_alo);
    cudaGetSymbolAddress((void**)&whi, g_whi);
    cudaGetSymbolAddress((void**)&wlo, g_wlo);

    const dim3 ggrid((NN + 127) / 128, 2);

    // CSR build
    k_zero_deg<<<(NN + 255) / 256, 256>>>();
    k_hist<<<(NE + 255) / 256, 256>>>(dst);
    k_scan<<<1, 1024>>>();
    k_scatter<<<(NE + 255) / 256, 256>>>(src, dst);

    // layer 1
    k_prep_w<<<(DH * DIN + 255) / 256, 256>>>(W1, DIN, whi, wlo);
    k_agg_split<DIN><<<NN, DIN / 4>>>(h, ahi, alo);
    k_gemm_hmma<DIN><<<ggrid, 256>>>(ahi, alo, whi, wlo, b1, h1);

    // layer 2
    k_prep_w<<<(DH * DH + 255) / 256, 256>>>(W2, DH, whi, wlo);
    k_agg_split<DH><<<NN, DH / 4>>>(h1, ahi, alo);
    k_gemm_hmma<DH><<<ggrid, 256>>>(ahi, alo, whi, wlo, b2, h2);

    // readout + MLP
    k_readout<<<NG, DH>>>(gids);
    k_mlp<<<NG, DH2>>>(Wr1, br1, Wr2, br2, out);
}

// round 4
// speedup vs baseline: 1.7921x; 1.0648x over previous
#include <cuda_runtime.h>
#include <cuda_bf16.h>
#include <cstdint>

#define NN   50000
#define NE   800000
#define DIN  128
#define DH   256
#define NG   256
#define DH2  128

// ---------------- scratch (device globals; no allocations allowed) ----------
__device__ __nv_bfloat16 g_h1  [(size_t)NN * DH];   // layer-1 output, bf16
__device__ __nv_bfloat16 g_h2  [(size_t)NN * DH];   // layer-2 output, bf16
__device__ __nv_bfloat16 g_ahi [(size_t)NN * DH];
__device__ __nv_bfloat16 g_alo [(size_t)NN * DH];
__device__ __nv_bfloat16 g_whi1[DH * DIN];
__device__ __nv_bfloat16 g_wlo1[DH * DIN];
__device__ __nv_bfloat16 g_whi2[DH * DH];
__device__ __nv_bfloat16 g_wlo2[DH * DH];
__device__ int   g_deg [NN];
__device__ int   g_rowptr[NN + 1];
__device__ int   g_pos [NN];
__device__ int   g_esrc[NE];
__device__ float g_hg  [NG * DH];

// ---------------- helpers ---------------------------------------------------
__device__ __forceinline__ uint32_t smem_u32(const void* p) {
    uint32_t a;
    asm("{ .reg .u64 t; cvta.to.shared.u64 t, %1; cvt.u32.u64 %0, t; }"
        : "=r"(a) : "l"(p));
    return a;
}

__device__ __forceinline__ void ldm_x4(uint32_t* f, uint32_t sa) {
    asm volatile("ldmatrix.sync.aligned.m8n8.x4.shared.b16 {%0,%1,%2,%3}, [%4];"
                 : "=r"(f[0]), "=r"(f[1]), "=r"(f[2]), "=r"(f[3]) : "r"(sa));
}

__device__ __forceinline__ void mma16816(float* c, const uint32_t* a, const uint32_t* b) {
    asm volatile(
        "mma.sync.aligned.m16n8k16.row.col.f32.bf16.bf16.f32 "
        "{%0,%1,%2,%3}, {%4,%5,%6,%7}, {%8,%9}, {%0,%1,%2,%3};"
        : "+f"(c[0]), "+f"(c[1]), "+f"(c[2]), "+f"(c[3])
        : "r"(a[0]), "r"(a[1]), "r"(a[2]), "r"(a[3]), "r"(b[0]), "r"(b[1]));
}

__device__ __forceinline__ void cp16(uint32_t d, const void* s, bool p) {
    asm volatile("cp.async.cg.shared.global [%0], [%1], 16, %2;"
                 :: "r"(d), "l"(s), "r"(p ? 16 : 0));
}
__device__ __forceinline__ void cp_commit() { asm volatile("cp.async.commit_group;"); }
template <int N>
__device__ __forceinline__ void cp_wait() { asm volatile("cp.async.wait_group %0;" :: "n"(N)); }

// ---------------- CSR build -------------------------------------------------
__global__ void k_zero_deg() {
    int i = blockIdx.x * blockDim.x + threadIdx.x;
    if (i < NN) g_deg[i] = 0;
}

__global__ void k_hist(const int* __restrict__ dst) {
    int e = blockIdx.x * blockDim.x + threadIdx.x;
    if (e < NE) atomicAdd(&g_deg[dst[e]], 1);
}

// chunked single-block scan: 1024 threads * 49 elems
__global__ void k_scan() {
    const int CH = 49;
    int t = threadIdx.x;
    int beg = t * CH;
    int end = beg + CH; if (end > NN) end = NN;
    int s = 0;
    for (int i = beg; i < end; ++i) s += g_deg[i];
    int lane = t & 31, w = t >> 5;
    int v = s;
#pragma unroll
    for (int o = 1; o < 32; o <<= 1) {
        int u = __shfl_up_sync(0xffffffffu, v, o);
        if (lane >= o) v += u;
    }
    __shared__ int wsum[32];
    if (lane == 31) wsum[w] = v;
    __syncthreads();
    if (w == 0) {
        int x = wsum[lane];
#pragma unroll
        for (int o = 1; o < 32; o <<= 1) {
            int u = __shfl_up_sync(0xffffffffu, x, o);
            if (lane >= o) x += u;
        }
        wsum[lane] = x;
    }
    __syncthreads();
    int excl = v - s + (w > 0 ? wsum[w - 1] : 0);
    for (int i = beg; i < end; ++i) {
        int d = g_deg[i];
        g_rowptr[i] = excl;
        g_pos[i]    = excl;
        excl += d;
    }
    if (t == 1023) g_rowptr[NN] = wsum[31];
}

__global__ void k_scatter(const int* __restrict__ src, const int* __restrict__ dst) {
    int e = blockIdx.x * blockDim.x + threadIdx.x;
    if (e < NE) {
        int p = atomicAdd(&g_pos[dst[e]], 1);
        g_esrc[p] = src[e];
    }
}

// ------------- layer-1 mean aggregation (f32 in) + bf16 hi/lo split ---------
__global__ void k_agg_split_f32(const float* __restrict__ hin,
                                __nv_bfloat16* __restrict__ hi,
                                __nv_bfloat16* __restrict__ lo) {
    int node = blockIdx.x;
    int f4   = threadIdx.x;              // DIN/4 = 32 threads
    int beg  = g_rowptr[node];
    int end  = g_rowptr[node + 1];
    float4 acc = make_float4(0.f, 0.f, 0.f, 0.f);
    int e = beg;
    for (; e + 1 < end; e += 2) {
        int s0 = g_esrc[e], s1 = g_esrc[e + 1];
        float4 v0 = __ldg((const float4*)(hin + (size_t)s0 * DIN) + f4);
        float4 v1 = __ldg((const float4*)(hin + (size_t)s1 * DIN) + f4);
        acc.x += v0.x + v1.x; acc.y += v0.y + v1.y;
        acc.z += v0.z + v1.z; acc.w += v0.w + v1.w;
    }
    if (e < end) {
        float4 v0 = __ldg((const float4*)(hin + (size_t)g_esrc[e] * DIN) + f4);
        acc.x += v0.x; acc.y += v0.y; acc.z += v0.z; acc.w += v0.w;
    }
    float inv = (end > beg) ? (1.f / (float)(end - beg)) : 0.f;
    float m[4] = { acc.x * inv, acc.y * inv, acc.z * inv, acc.w * inv };
    __nv_bfloat16 hv[4], lv[4];
#pragma unroll
    for (int j = 0; j < 4; ++j) {
        hv[j] = __float2bfloat16(m[j]);
        lv[j] = __float2bfloat16(m[j] - __bfloat162float(hv[j]));
    }
    *(uint2*)(hi + (size_t)node * DIN + 4 * f4) = *(uint2*)hv;
    *(uint2*)(lo + (size_t)node * DIN + 4 * f4) = *(uint2*)lv;
}

// ------------- layer-2 mean aggregation (bf16 in) + bf16 hi/lo split --------
__global__ void k_agg_split_b16(const __nv_bfloat16* __restrict__ hin,
                                __nv_bfloat16* __restrict__ hi,
                                __nv_bfloat16* __restrict__ lo) {
    int node = blockIdx.x;
    int f4   = threadIdx.x;              // DH/4 = 64 threads
    int beg  = g_rowptr[node];
    int end  = g_rowptr[node + 1];
    float4 acc = make_float4(0.f, 0.f, 0.f, 0.f);
    int e = beg;
    for (; e + 1 < end; e += 2) {
        int s0 = g_esrc[e], s1 = g_esrc[e + 1];
        uint2 u0 = __ldg((const uint2*)(hin + (size_t)s0 * DH) + f4);
        uint2 u1 = __ldg((const uint2*)(hin + (size_t)s1 * DH) + f4);
        float2 a0 = __bfloat1622float2(*(__nv_bfloat162*)&u0.x);
        float2 a1 = __bfloat1622float2(*(__nv_bfloat162*)&u0.y);
        float2 b0 = __bfloat1622float2(*(__nv_bfloat162*)&u1.x);
        float2 b1 = __bfloat1622float2(*(__nv_bfloat162*)&u1.y);
        acc.x += a0.x + b0.x; acc.y += a0.y + b0.y;
        acc.z += a1.x + b1.x; acc.w += a1.y + b1.y;
    }
    if (e < end) {
        uint2 u0 = __ldg((const uint2*)(hin + (size_t)g_esrc[e] * DH) + f4);
        float2 a0 = __bfloat1622float2(*(__nv_bfloat162*)&u0.x);
        float2 a1 = __bfloat1622float2(*(__nv_bfloat162*)&u0.y);
        acc.x += a0.x; acc.y += a0.y; acc.z += a1.x; acc.w += a1.y;
    }
    float inv = (end > beg) ? (1.f / (float)(end - beg)) : 0.f;
    float m[4] = { acc.x * inv, acc.y * inv, acc.z * inv, acc.w * inv };
    __nv_bfloat16 hv[4], lv[4];
#pragma unroll
    for (int j = 0; j < 4; ++j) {
        hv[j] = __float2bfloat16(m[j]);
        lv[j] = __float2bfloat16(m[j] - __bfloat162float(hv[j]));
    }
    *(uint2*)(hi + (size_t)node * DH + 4 * f4) = *(uint2*)hv;
    *(uint2*)(lo + (size_t)node * DH + 4 * f4) = *(uint2*)lv;
}

// -------- weight transpose + split: Wt[n][k] = W[k][n], bf16 hi/lo ----------
__global__ void k_prep_w(const float* __restrict__ W, int K,
                         __nv_bfloat16* __restrict__ hi,
                         __nv_bfloat16* __restrict__ lo) {
    int idx = blockIdx.x * blockDim.x + threadIdx.x;
    if (idx < DH * K) {
        int n = idx / K, k = idx % K;
        float v = W[(size_t)k * DH + n];
        __nv_bfloat16 h = __float2bfloat16(v);
        hi[idx] = h;
        lo[idx] = __float2bfloat16(v - __bfloat162float(h));
    }
}

// ---------------- HMMA GEMM (cp.async 2-stage): C = relu(A@Wt^T + b) --------
// A: [NN x K] bf16 hi/lo; Wt: [256 x K] bf16 hi/lo; C: [NN x 256] bf16
#define LDA      40                 // 32 + 8 pad (bf16); row stride 80 B
#define TILE_B   (128 * LDA * 2)    // 10240 bytes
#define STAGE_B  (4 * TILE_B)       // 40960 bytes
#define GEMM_SMEM (2 * STAGE_B)     // 81920 bytes

template <int K>
__global__ __launch_bounds__(256) void k_gemm_hmma(
    const __nv_bfloat16* __restrict__ Ahi, const __nv_bfloat16* __restrict__ Alo,
    const __nv_bfloat16* __restrict__ Bhi, const __nv_bfloat16* __restrict__ Blo,
    const float* __restrict__ bias, __nv_bfloat16* __restrict__ C)
{
    extern __shared__ char dsm[];
    const uint32_t sb0 = smem_u32(dsm);

    const int tid  = threadIdx.x;
    const int lane = tid & 31;
    const int wid  = tid >> 5;
    const int wm   = (wid >> 1) * 32;
    const int wn   = (wid & 1) * 64;
    const int m0   = blockIdx.x * 128;
    const int n0   = blockIdx.y * 128;

    float c[2][8][4];
#pragma unroll
    for (int i = 0; i < 2; ++i)
#pragma unroll
        for (int j = 0; j < 8; ++j)
#pragma unroll
            for (int q = 0; q < 4; ++q) c[i][j][q] = 0.f;

    // ldmatrix per-lane tile-relative byte offsets
    const int aq = lane >> 3, ar = lane & 7;
    const int a_row = ar + (aq & 1) * 8;
    const int a_col = (aq >> 1) * 8;
    uint32_t aoff[2];
#pragma unroll
    for (int i = 0; i < 2; ++i)
        aoff[i] = (uint32_t)(((wm + i * 16 + a_row) * LDA + a_col) * 2);
    const int b_row = (aq >> 1) * 8 + ar;
    const int b_col = (aq & 1) * 8;
    uint32_t boff[4];
#pragma unroll
    for (int jp = 0; jp < 4; ++jp)
        boff[jp] = (uint32_t)(((wn + jp * 16 + b_row) * LDA + b_col) * 2);

    auto load_stage = [&](int k0, int s) {
        uint32_t base = sb0 + (uint32_t)s * STAGE_B;
#pragma unroll
        for (int t = 0; t < 2; ++t) {
            int idx = t * 256 + tid;          // 0..511
            int r = idx >> 2, cB = (idx & 3) * 8;
            uint32_t so = (uint32_t)((r * LDA + cB) * 2);
            int gr = m0 + r;
            bool ap = gr < NN;
            int grc = ap ? gr : (NN - 1);
            size_t aoffg = (size_t)grc * K + k0 + cB;
            cp16(base + so,              Ahi + aoffg, ap);
            cp16(base + TILE_B + so,     Alo + aoffg, ap);
            size_t boffg = (size_t)(n0 + r) * K + k0 + cB;
            cp16(base + 2 * TILE_B + so, Bhi + boffg, true);
            cp16(base + 3 * TILE_B + so, Blo + boffg, true);
        }
        cp_commit();
    };

    load_stage(0, 0);
    const int NCH = K / 32;
    for (int ch = 0; ch < NCH; ++ch) {
        if (ch + 1 < NCH) { load_stage((ch + 1) * 32, (ch + 1) & 1); cp_wait<1>(); }
        else              { cp_wait<0>(); }
        __syncthreads();
        uint32_t base  = sb0 + (uint32_t)(ch & 1) * STAGE_B;
        uint32_t sa_hi = base,              sa_lo = base + TILE_B;
        uint32_t sb_hi = base + 2 * TILE_B, sb_lo = base + 3 * TILE_B;
#pragma unroll
        for (int ks = 0; ks < 2; ++ks) {
            uint32_t ahi[2][4], alo[2][4];
#pragma unroll
            for (int i = 0; i < 2; ++i) {
                ldm_x4(ahi[i], sa_hi + aoff[i] + ks * 32);
                ldm_x4(alo[i], sa_lo + aoff[i] + ks * 32);
            }
#pragma unroll
            for (int jp = 0; jp < 4; ++jp) {
                uint32_t bhi[4], blo[4];
                ldm_x4(bhi, sb_hi + boff[jp] + ks * 32);
                ldm_x4(blo, sb_lo + boff[jp] + ks * 32);
#pragma unroll
                for (int i = 0; i < 2; ++i) {
#pragma unroll
                    for (int jj = 0; jj < 2; ++jj) {
                        float* cc = c[i][jp * 2 + jj];
                        mma16816(cc, ahi[i], bhi + jj * 2);  // hi*hi
                        mma16816(cc, ahi[i], blo + jj * 2);  // hi*lo
                        mma16816(cc, alo[i], bhi + jj * 2);  // lo*hi
                    }
                }
            }
        }
        __syncthreads();
    }

    // epilogue: bias + relu, bf16 store
    const int g   = lane >> 2;
    const int tig = lane & 3;
#pragma unroll
    for (int i = 0; i < 2; ++i) {
#pragma unroll
        for (int j = 0; j < 8; ++j) {
            int col  = n0 + wn + j * 8 + 2 * tig;
            float b0 = bias[col], b1 = bias[col + 1];
            int r0 = m0 + wm + i * 16 + g;
            if (r0 < NN) {
                __nv_bfloat162 o = __floats2bfloat162_rn(
                    fmaxf(c[i][j][0] + b0, 0.f), fmaxf(c[i][j][1] + b1, 0.f));
                *(__nv_bfloat162*)(C + (size_t)r0 * 256 + col) = o;
            }
            int r1 = r0 + 8;
            if (r1 < NN) {
                __nv_bfloat162 o = __floats2bfloat162_rn(
                    fmaxf(c[i][j][2] + b0, 0.f), fmaxf(c[i][j][3] + b1, 0.f));
                *(__nv_bfloat162*)(C + (size_t)r1 * 256 + col) = o;
            }
        }
    }
}

// ---------------- per-graph mean readout (graph_ids sorted) -----------------
__global__ void k_readout(const int* __restrict__ gids) {
    int g = blockIdx.x;
    __shared__ int sb_, se_;
    if (threadIdx.x == 0) {
        int lo = 0, hi = NN;
        while (lo < hi) { int mid = (lo + hi) >> 1; if (gids[mid] < g) lo = mid + 1; else hi = mid; }
        sb_ = lo;
        lo = 0; hi = NN;
        while (lo < hi) { int mid = (lo + hi) >> 1; if (gids[mid] < g + 1) lo = mid + 1; else hi = mid; }
        se_ = lo;
    }
    __syncthreads();
    int beg = sb_, end = se_;
    int f = threadIdx.x;
    float acc = 0.f;
    for (int n = beg; n < end; ++n)
        acc += __bfloat162float(g_h2[(size_t)n * DH + f]);
    float cnt = (float)(end - beg);
    g_hg[g * DH + f] = acc / fmaxf(cnt, 1.f);
}

// ---------------- final MLP: out[g] = (hg@Wr1+br1)@Wr2 + br2 ---------------
__global__ void k_mlp(const float* __restrict__ Wr1, const float* __restrict__ br1,
                      const float* __restrict__ Wr2, const float* __restrict__ br2,
                      float* __restrict__ out) {
    int g = blockIdx.x;
    int j = threadIdx.x;
    __shared__ float shg[DH];
    shg[j]       = g_hg[g * DH + j];
    shg[j + 128] = g_hg[g * DH + j + 128];
    __syncthreads();
    float acc = br1[j];
#pragma unroll 4
    for (int k = 0; k < DH; ++k) acc += shg[k] * Wr1[k * DH2 + j];
    float v = acc * Wr2[j];
#pragma unroll
    for (int off = 16; off > 0; off >>= 1) v += __shfl_down_sync(0xffffffffu, v, off);
    __shared__ float ws[4];
    if ((j & 31) == 0) ws[j >> 5] = v;
    __syncthreads();
    if (j == 0) out[g] = ws[0] + ws[1] + ws[2] + ws[3] + br2[0];
}

// ---------------- launch ----------------------------------------------------
extern "C" void kernel_launch(void* const* d_in, const int* in_sizes, int n_in,
                              void* d_out, int out_size) {
    const float* h    = (const float*)d_in[0];
    const int*   src  = (const int*)  d_in[1];
    const int*   dst  = (const int*)  d_in[2];
    const int*   gids = (const int*)  d_in[3];
    const float* W1   = (const float*)d_in[4];
    const float* b1   = (const float*)d_in[5];
    const float* W2   = (const float*)d_in[6];
    const float* b2   = (const float*)d_in[7];
    const float* Wr1  = (const float*)d_in[8];
    const float* br1  = (const float*)d_in[9];
    const float* Wr2  = (const float*)d_in[10];
    const float* br2  = (const float*)d_in[11];
    float* out = (float*)d_out;

    __nv_bfloat16 *h1, *h2, *ahi, *alo, *whi1, *wlo1, *whi2, *wlo2;
    cudaGetSymbolAddress((void**)&h1,   g_h1);
    cudaGetSymbolAddress((void**)&h2,   g_h2);
    cudaGetSymbolAddress((void**)&ahi,  g_ahi);
    cudaGetSymbolAddress((void**)&alo,  g_alo);
    cudaGetSymbolAddress((void**)&whi1, g_whi1);
    cudaGetSymbolAddress((void**)&wlo1, g_wlo1);
    cudaGetSymbolAddress((void**)&whi2, g_whi2);
    cudaGetSymbolAddress((void**)&wlo2, g_wlo2);

    cudaFuncSetAttribute(k_gemm_hmma<DIN>, cudaFuncAttributeMaxDynamicSharedMemorySize, GEMM_SMEM);
    cudaFuncSetAttribute(k_gemm_hmma<DH>,  cudaFuncAttributeMaxDynamicSharedMemorySize, GEMM_SMEM);

    const dim3 ggrid((NN + 127) / 128, 2);

    // CSR build
    k_zero_deg<<<(NN + 255) / 256, 256>>>();
    k_hist<<<(NE + 255) / 256, 256>>>(dst);
    k_scan<<<1, 1024>>>();
    k_scatter<<<(NE + 255) / 256, 256>>>(src, dst);

    // weight prep (independent of CSR)
    k_prep_w<<<(DH * DIN + 255) / 256, 256>>>(W1, DIN, whi1, wlo1);
    k_prep_w<<<(DH * DH + 255) / 256, 256>>>(W2, DH, whi2, wlo2);

    // layer 1
    k_agg_split_f32<<<NN, DIN / 4>>>(h, ahi, alo);
    k_gemm_hmma<DIN><<<ggrid, 256, GEMM_SMEM>>>(ahi, alo, whi1, wlo1, b1, h1);

    // layer 2
    k_agg_split_b16<<<NN, DH / 4>>>(h1, ahi, alo);
    k_gemm_hmma<DH><<<ggrid, 256, GEMM_SMEM>>>(ahi, alo, whi2, wlo2, b2, h2);

    // readout + MLP
    k_readout<<<NG, DH>>>(gids);
    k_mlp<<<NG, DH2>>>(Wr1, br1, Wr2, br2, out);
}

// round 5
// speedup vs baseline: 1.9953x; 1.1134x over previous
#include <cuda_runtime.h>
#include <cuda_bf16.h>
#include <cstdint>

#define NN   50000
#define NE   800000
#define DIN  128
#define DH   256
#define NG   256
#define DH2  128

// ---------------- scratch (device globals; no allocations allowed) ----------
__device__ __nv_bfloat16 g_hb  [(size_t)NN * DIN];  // input h, bf16
__device__ __nv_bfloat16 g_a   [(size_t)NN * DH];   // aggregated features, bf16
__device__ __nv_bfloat16 g_h1  [(size_t)NN * DH];   // layer-1 output, bf16
__device__ __nv_bfloat16 g_h2  [(size_t)NN * DH];   // layer-2 output, bf16
__device__ __nv_bfloat16 g_whi1[DH * DIN];
__device__ __nv_bfloat16 g_wlo1[DH * DIN];
__device__ __nv_bfloat16 g_whi2[DH * DH];
__device__ __nv_bfloat16 g_wlo2[DH * DH];
__device__ int   g_deg [NN];
__device__ int   g_rowptr[NN + 1];
__device__ int   g_pos [NN];
__device__ int   g_esrc[NE];
__device__ float g_hg  [NG * DH];

// ---------------- helpers ---------------------------------------------------
__device__ __forceinline__ uint32_t smem_u32(const void* p) {
    uint32_t a;
    asm("{ .reg .u64 t; cvta.to.shared.u64 t, %1; cvt.u32.u64 %0, t; }"
        : "=r"(a) : "l"(p));
    return a;
}

__device__ __forceinline__ void ldm_x4(uint32_t* f, uint32_t sa) {
    asm volatile("ldmatrix.sync.aligned.m8n8.x4.shared.b16 {%0,%1,%2,%3}, [%4];"
                 : "=r"(f[0]), "=r"(f[1]), "=r"(f[2]), "=r"(f[3]) : "r"(sa));
}

__device__ __forceinline__ void mma16816(float* c, const uint32_t* a, const uint32_t* b) {
    asm volatile(
        "mma.sync.aligned.m16n8k16.row.col.f32.bf16.bf16.f32 "
        "{%0,%1,%2,%3}, {%4,%5,%6,%7}, {%8,%9}, {%0,%1,%2,%3};"
        : "+f"(c[0]), "+f"(c[1]), "+f"(c[2]), "+f"(c[3])
        : "r"(a[0]), "r"(a[1]), "r"(a[2]), "r"(a[3]), "r"(b[0]), "r"(b[1]));
}

__device__ __forceinline__ void cp16(uint32_t d, const void* s, bool p) {
    asm volatile("cp.async.cg.shared.global [%0], [%1], 16, %2;"
                 :: "r"(d), "l"(s), "r"(p ? 16 : 0));
}
__device__ __forceinline__ void cp_commit() { asm volatile("cp.async.commit_group;"); }
template <int N>
__device__ __forceinline__ void cp_wait() { asm volatile("cp.async.wait_group %0;" :: "n"(N)); }

// ---------------- CSR build -------------------------------------------------
__global__ void k_zero_deg() {
    int i = blockIdx.x * blockDim.x + threadIdx.x;
    if (i < NN) g_deg[i] = 0;
}

__global__ void k_hist(const int* __restrict__ dst) {
    int e = blockIdx.x * blockDim.x + threadIdx.x;
    if (e < NE) atomicAdd(&g_deg[dst[e]], 1);
}

// chunked single-block scan: 1024 threads * 49 elems
__global__ void k_scan() {
    const int CH = 49;
    int t = threadIdx.x;
    int beg = t * CH;
    int end = beg + CH; if (end > NN) end = NN;
    int s = 0;
    for (int i = beg; i < end; ++i) s += g_deg[i];
    int lane = t & 31, w = t >> 5;
    int v = s;
#pragma unroll
    for (int o = 1; o < 32; o <<= 1) {
        int u = __shfl_up_sync(0xffffffffu, v, o);
        if (lane >= o) v += u;
    }
    __shared__ int wsum[32];
    if (lane == 31) wsum[w] = v;
    __syncthreads();
    if (w == 0) {
        int x = wsum[lane];
#pragma unroll
        for (int o = 1; o < 32; o <<= 1) {
            int u = __shfl_up_sync(0xffffffffu, x, o);
            if (lane >= o) x += u;
        }
        wsum[lane] = x;
    }
    __syncthreads();
    int excl = v - s + (w > 0 ? wsum[w - 1] : 0);
    for (int i = beg; i < end; ++i) {
        int d = g_deg[i];
        g_rowptr[i] = excl;
        g_pos[i]    = excl;
        excl += d;
    }
    if (t == 1023) g_rowptr[NN] = wsum[31];
}

__global__ void k_scatter(const int* __restrict__ src, const int* __restrict__ dst) {
    int e = blockIdx.x * blockDim.x + threadIdx.x;
    if (e < NE) {
        int p = atomicAdd(&g_pos[dst[e]], 1);
        g_esrc[p] = src[e];
    }
}

// ---------------- input h -> bf16 -------------------------------------------
__global__ void k_prep_h(const float* __restrict__ h) {
    int i = blockIdx.x * blockDim.x + threadIdx.x;   // over NN*DIN/4
    if (i < NN * DIN / 4) {
        float4 v = __ldg((const float4*)h + i);
        __nv_bfloat16 b[4] = { __float2bfloat16(v.x), __float2bfloat16(v.y),
                               __float2bfloat16(v.z), __float2bfloat16(v.w) };
        *(uint2*)(g_hb + 4 * (size_t)i) = *(uint2*)b;
    }
}

// ------------- warp-per-node mean aggregation (bf16 in/out) -----------------
// F=128: lane handles 4 bf16 (uint2); F=256: 8 bf16 (uint4)
template <int F>
__global__ __launch_bounds__(256) void k_agg(const __nv_bfloat16* __restrict__ hin,
                                             __nv_bfloat16* __restrict__ outp) {
    int warp = (blockIdx.x * blockDim.x + threadIdx.x) >> 5;
    if (warp >= NN) return;
    int lane = threadIdx.x & 31;
    int beg = g_rowptr[warp];
    int end = g_rowptr[warp + 1];
    constexpr int V = F / 32;          // bf16 per lane: 4 or 8
    float acc[V];
#pragma unroll
    for (int j = 0; j < V; ++j) acc[j] = 0.f;

    for (int e = beg; e < end; ++e) {
        int s = g_esrc[e];
        const __nv_bfloat16* row = hin + (size_t)s * F + lane * V;
        if constexpr (V == 4) {
            uint2 u = __ldg((const uint2*)row);
            float2 a = __bfloat1622float2(*(__nv_bfloat162*)&u.x);
            float2 b = __bfloat1622float2(*(__nv_bfloat162*)&u.y);
            acc[0] += a.x; acc[1] += a.y; acc[2] += b.x; acc[3] += b.y;
        } else {
            uint4 u = __ldg((const uint4*)row);
            float2 a = __bfloat1622float2(*(__nv_bfloat162*)&u.x);
            float2 b = __bfloat1622float2(*(__nv_bfloat162*)&u.y);
            float2 c = __bfloat1622float2(*(__nv_bfloat162*)&u.z);
            float2 d = __bfloat1622float2(*(__nv_bfloat162*)&u.w);
            acc[0] += a.x; acc[1] += a.y; acc[2] += b.x; acc[3] += b.y;
            acc[4] += c.x; acc[5] += c.y; acc[6] += d.x; acc[7] += d.y;
        }
    }
    float inv = (end > beg) ? (1.f / (float)(end - beg)) : 0.f;
    __nv_bfloat16 o[V];
#pragma unroll
    for (int j = 0; j < V; ++j) o[j] = __float2bfloat16(acc[j] * inv);
    if constexpr (V == 4)
        *(uint2*)(outp + (size_t)warp * F + lane * V) = *(uint2*)o;
    else
        *(uint4*)(outp + (size_t)warp * F + lane * V) = *(uint4*)o;
}

// -------- weight transpose + split: Wt[n][k] = W[k][n], bf16 hi/lo ----------
__global__ void k_prep_w(const float* __restrict__ W, int K,
                         __nv_bfloat16* __restrict__ hi,
                         __nv_bfloat16* __restrict__ lo) {
    int idx = blockIdx.x * blockDim.x + threadIdx.x;
    if (idx < DH * K) {
        int n = idx / K, k = idx % K;
        float v = W[(size_t)k * DH + n];
        __nv_bfloat16 h = __float2bfloat16(v);
        hi[idx] = h;
        lo[idx] = __float2bfloat16(v - __bfloat162float(h));
    }
}

// ------- HMMA GEMM (cp.async 2-stage): C = relu(A @ (Whi+Wlo)^T + b) --------
// A: [NN x K] bf16; Wt: [256 x K] bf16 hi/lo; C: [NN x 256] bf16
#define LDA      40                 // 32 + 8 pad (bf16); row stride 80 B
#define TILE_B   (128 * LDA * 2)    // 10240 bytes
#define STAGE_B  (3 * TILE_B)       // 30720 bytes: A, Bhi, Blo
#define GEMM_SMEM (2 * STAGE_B)     // 61440 bytes

template <int K>
__global__ __launch_bounds__(256) void k_gemm_hmma(
    const __nv_bfloat16* __restrict__ A,
    const __nv_bfloat16* __restrict__ Bhi, const __nv_bfloat16* __restrict__ Blo,
    const float* __restrict__ bias, __nv_bfloat16* __restrict__ C)
{
    extern __shared__ char dsm[];
    const uint32_t sb0 = smem_u32(dsm);

    const int tid  = threadIdx.x;
    const int lane = tid & 31;
    const int wid  = tid >> 5;
    const int wm   = (wid >> 1) * 32;
    const int wn   = (wid & 1) * 64;
    const int m0   = blockIdx.x * 128;
    const int n0   = blockIdx.y * 128;

    float c[2][8][4];
#pragma unroll
    for (int i = 0; i < 2; ++i)
#pragma unroll
        for (int j = 0; j < 8; ++j)
#pragma unroll
            for (int q = 0; q < 4; ++q) c[i][j][q] = 0.f;

    const int aq = lane >> 3, ar = lane & 7;
    const int a_row = ar + (aq & 1) * 8;
    const int a_col = (aq >> 1) * 8;
    uint32_t aoff[2];
#pragma unroll
    for (int i = 0; i < 2; ++i)
        aoff[i] = (uint32_t)(((wm + i * 16 + a_row) * LDA + a_col) * 2);
    const int b_row = (aq >> 1) * 8 + ar;
    const int b_col = (aq & 1) * 8;
    uint32_t boff[4];
#pragma unroll
    for (int jp = 0; jp < 4; ++jp)
        boff[jp] = (uint32_t)(((wn + jp * 16 + b_row) * LDA + b_col) * 2);

    auto load_stage = [&](int k0, int s) {
        uint32_t base = sb0 + (uint32_t)s * STAGE_B;
#pragma unroll
        for (int t = 0; t < 2; ++t) {
            int idx = t * 256 + tid;          // 0..511
            int r = idx >> 2, cB = (idx & 3) * 8;
            uint32_t so = (uint32_t)((r * LDA + cB) * 2);
            int gr = m0 + r;
            bool ap = gr < NN;
            int grc = ap ? gr : (NN - 1);
            cp16(base + so, A + (size_t)grc * K + k0 + cB, ap);
            size_t boffg = (size_t)(n0 + r) * K + k0 + cB;
            cp16(base + TILE_B + so,     Bhi + boffg, true);
            cp16(base + 2 * TILE_B + so, Blo + boffg, true);
        }
        cp_commit();
    };

    load_stage(0, 0);
    const int NCH = K / 32;
    for (int ch = 0; ch < NCH; ++ch) {
        if (ch + 1 < NCH) { load_stage((ch + 1) * 32, (ch + 1) & 1); cp_wait<1>(); }
        else              { cp_wait<0>(); }
        __syncthreads();
        uint32_t base  = sb0 + (uint32_t)(ch & 1) * STAGE_B;
        uint32_t sa    = base;
        uint32_t sb_hi = base + TILE_B, sb_lo = base + 2 * TILE_B;
#pragma unroll
        for (int ks = 0; ks < 2; ++ks) {
            uint32_t af[2][4];
#pragma unroll
            for (int i = 0; i < 2; ++i) ldm_x4(af[i], sa + aoff[i] + ks * 32);
#pragma unroll
            for (int jp = 0; jp < 4; ++jp) {
                uint32_t bhi[4], blo[4];
                ldm_x4(bhi, sb_hi + boff[jp] + ks * 32);
                ldm_x4(blo, sb_lo + boff[jp] + ks * 32);
#pragma unroll
                for (int i = 0; i < 2; ++i) {
#pragma unroll
                    for (int jj = 0; jj < 2; ++jj) {
                        float* cc = c[i][jp * 2 + jj];
                        mma16816(cc, af[i], bhi + jj * 2);
                        mma16816(cc, af[i], blo + jj * 2);
                    }
                }
            }
        }
        __syncthreads();
    }

    // epilogue: bias + relu, bf16 store
    const int g   = lane >> 2;
    const int tig = lane & 3;
#pragma unroll
    for (int i = 0; i < 2; ++i) {
#pragma unroll
        for (int j = 0; j < 8; ++j) {
            int col  = n0 + wn + j * 8 + 2 * tig;
            float b0 = bias[col], b1 = bias[col + 1];
            int r0 = m0 + wm + i * 16 + g;
            if (r0 < NN) {
                __nv_bfloat162 o = __floats2bfloat162_rn(
                    fmaxf(c[i][j][0] + b0, 0.f), fmaxf(c[i][j][1] + b1, 0.f));
                *(__nv_bfloat162*)(C + (size_t)r0 * 256 + col) = o;
            }
            int r1 = r0 + 8;
            if (r1 < NN) {
                __nv_bfloat162 o = __floats2bfloat162_rn(
                    fmaxf(c[i][j][2] + b0, 0.f), fmaxf(c[i][j][3] + b1, 0.f));
                *(__nv_bfloat162*)(C + (size_t)r1 * 256 + col) = o;
            }
        }
    }
}

// ---------------- per-graph mean readout (graph_ids sorted) -----------------
__global__ void k_readout(const int* __restrict__ gids) {
    int g = blockIdx.x;
    __shared__ int sb_, se_;
    if (threadIdx.x == 0) {
        int lo = 0, hi = NN;
        while (lo < hi) { int mid = (lo + hi) >> 1; if (gids[mid] < g) lo = mid + 1; else hi = mid; }
        sb_ = lo;
        lo = 0; hi = NN;
        while (lo < hi) { int mid = (lo + hi) >> 1; if (gids[mid] < g + 1) lo = mid + 1; else hi = mid; }
        se_ = lo;
    }
    __syncthreads();
    int beg = sb_, end = se_;
    int f = threadIdx.x;
    float acc = 0.f;
    for (int n = beg; n < end; ++n)
        acc += __bfloat162float(g_h2[(size_t)n * DH + f]);
    float cnt = (float)(end - beg);
    g_hg[g * DH + f] = acc / fmaxf(cnt, 1.f);
}

// ---------------- final MLP: out[g] = (hg@Wr1+br1)@Wr2 + br2 ---------------
__global__ void k_mlp(const float* __restrict__ Wr1, const float* __restrict__ br1,
                      const float* __restrict__ Wr2, const float* __restrict__ br2,
                      float* __restrict__ out) {
    int g = blockIdx.x;
    int j = threadIdx.x;
    __shared__ float shg[DH];
    shg[j]       = g_hg[g * DH + j];
    shg[j + 128] = g_hg[g * DH + j + 128];
    __syncthreads();
    float acc = br1[j];
#pragma unroll 4
    for (int k = 0; k < DH; ++k) acc += shg[k] * Wr1[k * DH2 + j];
    float v = acc * Wr2[j];
#pragma unroll
    for (int off = 16; off > 0; off >>= 1) v += __shfl_down_sync(0xffffffffu, v, off);
    __shared__ float ws[4];
    if ((j & 31) == 0) ws[j >> 5] = v;
    __syncthreads();
    if (j == 0) out[g] = ws[0] + ws[1] + ws[2] + ws[3] + br2[0];
}

// ---------------- launch ----------------------------------------------------
extern "C" void kernel_launch(void* const* d_in, const int* in_sizes, int n_in,
                              void* d_out, int out_size) {
    const float* h    = (const float*)d_in[0];
    const int*   src  = (const int*)  d_in[1];
    const int*   dst  = (const int*)  d_in[2];
    const int*   gids = (const int*)  d_in[3];
    const float* W1   = (const float*)d_in[4];
    const float* b1   = (const float*)d_in[5];
    const float* W2   = (const float*)d_in[6];
    const float* b2   = (const float*)d_in[7];
    const float* Wr1  = (const float*)d_in[8];
    const float* br1  = (const float*)d_in[9];
    const float* Wr2  = (const float*)d_in[10];
    const float* br2  = (const float*)d_in[11];
    float* out = (float*)d_out;

    __nv_bfloat16 *hb, *a, *h1, *h2, *whi1, *wlo1, *whi2, *wlo2;
    cudaGetSymbolAddress((void**)&hb,   g_hb);
    cudaGetSymbolAddress((void**)&a,    g_a);
    cudaGetSymbolAddress((void**)&h1,   g_h1);
    cudaGetSymbolAddress((void**)&h2,   g_h2);
    cudaGetSymbolAddress((void**)&whi1, g_whi1);
    cudaGetSymbolAddress((void**)&wlo1, g_wlo1);
    cudaGetSymbolAddress((void**)&whi2, g_whi2);
    cudaGetSymbolAddress((void**)&wlo2, g_wlo2);

    cudaFuncSetAttribute(k_gemm_hmma<DIN>, cudaFuncAttributeMaxDynamicSharedMemorySize, GEMM_SMEM);
    cudaFuncSetAttribute(k_gemm_hmma<DH>,  cudaFuncAttributeMaxDynamicSharedMemorySize, GEMM_SMEM);

    const dim3 ggrid((NN + 127) / 128, 2);
    const int AGG_BLK = (NN * 32 + 255) / 256;   // warp per node

    // CSR build
    k_zero_deg<<<(NN + 255) / 256, 256>>>();
    k_hist<<<(NE + 255) / 256, 256>>>(dst);
    k_scan<<<1, 1024>>>();
    k_scatter<<<(NE + 255) / 256, 256>>>(src, dst);

    // prep (independent of CSR)
    k_prep_h<<<(NN * DIN / 4 + 255) / 256, 256>>>(h);
    k_prep_w<<<(DH * DIN + 255) / 256, 256>>>(W1, DIN, whi1, wlo1);
    k_prep_w<<<(DH * DH + 255) / 256, 256>>>(W2, DH, whi2, wlo2);

    // layer 1
    k_agg<DIN><<<AGG_BLK, 256>>>(hb, a);
    k_gemm_hmma<DIN><<<ggrid, 256, GEMM_SMEM>>>(a, whi1, wlo1, b1, h1);

    // layer 2
    k_agg<DH><<<AGG_BLK, 256>>>(h1, a);
    k_gemm_hmma<DH><<<ggrid, 256, GEMM_SMEM>>>(a, whi2, wlo2, b2, h2);

    // readout + MLP
    k_readout<<<NG, DH>>>(gids);
    k_mlp<<<NG, DH2>>>(Wr1, br1, Wr2, br2, out);
}

// round 6
// speedup vs baseline: 2.3059x; 1.1557x over previous
#include <cuda_runtime.h>
#include <cuda_bf16.h>
#include <cstdint>

#define NN   50000
#define NE   800000
#define DIN  128
#define DH   256
#define NG   256
#define DH2  128

// ---------------- scratch (device globals; no allocations allowed) ----------
__device__ __nv_bfloat16 g_hb [(size_t)NN * DIN];  // input h, bf16
__device__ __nv_bfloat16 g_a  [(size_t)NN * DH];   // aggregated features, bf16
__device__ __nv_bfloat16 g_h1 [(size_t)NN * DH];   // layer-1 output, bf16
__device__ __nv_bfloat16 g_h2 [(size_t)NN * DH];   // layer-2 output, bf16
__device__ __nv_bfloat16 g_w1 [DH * DIN];          // W1^T bf16
__device__ __nv_bfloat16 g_w2 [DH * DH];           // W2^T bf16
__device__ int g_deg[NN];
__device__ int g_rowptr[NN + 1];
__device__ int g_pos[NN];
__device__ int g_esrc[NE];

// ---------------- helpers ---------------------------------------------------
__device__ __forceinline__ uint32_t smem_u32(const void* p) {
    uint32_t a;
    asm("{ .reg .u64 t; cvta.to.shared.u64 t, %1; cvt.u32.u64 %0, t; }"
        : "=r"(a) : "l"(p));
    return a;
}

__device__ __forceinline__ void ldm_x4(uint32_t* f, uint32_t sa) {
    asm volatile("ldmatrix.sync.aligned.m8n8.x4.shared.b16 {%0,%1,%2,%3}, [%4];"
                 : "=r"(f[0]), "=r"(f[1]), "=r"(f[2]), "=r"(f[3]) : "r"(sa));
}

__device__ __forceinline__ void mma16816(float* c, const uint32_t* a, const uint32_t* b) {
    asm volatile(
        "mma.sync.aligned.m16n8k16.row.col.f32.bf16.bf16.f32 "
        "{%0,%1,%2,%3}, {%4,%5,%6,%7}, {%8,%9}, {%0,%1,%2,%3};"
        : "+f"(c[0]), "+f"(c[1]), "+f"(c[2]), "+f"(c[3])
        : "r"(a[0]), "r"(a[1]), "r"(a[2]), "r"(a[3]), "r"(b[0]), "r"(b[1]));
}

__device__ __forceinline__ void cp16(uint32_t d, const void* s, bool p) {
    asm volatile("cp.async.cg.shared.global [%0], [%1], 16, %2;"
                 :: "r"(d), "l"(s), "r"(p ? 16 : 0));
}
__device__ __forceinline__ void cp_commit() { asm volatile("cp.async.commit_group;"); }
template <int N>
__device__ __forceinline__ void cp_wait() { asm volatile("cp.async.wait_group %0;" :: "n"(N)); }

// ---------------- fused prep: zero deg + h->bf16 + W1,W2 transpose ----------
#define PREP_H_ITEMS   (NN * DIN / 4)            // 1,600,000
#define PREP_W1_ITEMS  (DH * DIN)                // 32,768
#define PREP_W2_ITEMS  (DH * DH)                 // 65,536
#define PREP_TOTAL     (PREP_H_ITEMS + PREP_W1_ITEMS + PREP_W2_ITEMS + NN)

__global__ void k_prep(const float* __restrict__ h,
                       const float* __restrict__ W1,
                       const float* __restrict__ W2) {
    int i = blockIdx.x * blockDim.x + threadIdx.x;
    if (i < PREP_H_ITEMS) {
        float4 v = __ldg((const float4*)h + i);
        __nv_bfloat16 b[4] = { __float2bfloat16(v.x), __float2bfloat16(v.y),
                               __float2bfloat16(v.z), __float2bfloat16(v.w) };
        *(uint2*)(g_hb + 4 * (size_t)i) = *(uint2*)b;
        return;
    }
    i -= PREP_H_ITEMS;
    if (i < PREP_W1_ITEMS) {
        int n = i / DIN, k = i % DIN;
        g_w1[i] = __float2bfloat16(W1[(size_t)k * DH + n]);
        return;
    }
    i -= PREP_W1_ITEMS;
    if (i < PREP_W2_ITEMS) {
        int n = i / DH, k = i % DH;
        g_w2[i] = __float2bfloat16(W2[(size_t)k * DH + n]);
        return;
    }
    i -= PREP_W2_ITEMS;
    if (i < NN) g_deg[i] = 0;
}

// ---------------- CSR build -------------------------------------------------
__global__ void k_hist(const int* __restrict__ dst) {
    int e = blockIdx.x * blockDim.x + threadIdx.x;
    if (e < NE) atomicAdd(&g_deg[dst[e]], 1);
}

// chunked single-block scan: 1024 threads * 49 elems
__global__ void k_scan() {
    const int CH = 49;
    int t = threadIdx.x;
    int beg = t * CH;
    int end = beg + CH; if (end > NN) end = NN;
    int s = 0;
    for (int i = beg; i < end; ++i) s += g_deg[i];
    int lane = t & 31, w = t >> 5;
    int v = s;
#pragma unroll
    for (int o = 1; o < 32; o <<= 1) {
        int u = __shfl_up_sync(0xffffffffu, v, o);
        if (lane >= o) v += u;
    }
    __shared__ int wsum[32];
    if (lane == 31) wsum[w] = v;
    __syncthreads();
    if (w == 0) {
        int x = wsum[lane];
#pragma unroll
        for (int o = 1; o < 32; o <<= 1) {
            int u = __shfl_up_sync(0xffffffffu, x, o);
            if (lane >= o) x += u;
        }
        wsum[lane] = x;
    }
    __syncthreads();
    int excl = v - s + (w > 0 ? wsum[w - 1] : 0);
    for (int i = beg; i < end; ++i) {
        int d = g_deg[i];
        g_rowptr[i] = excl;
        g_pos[i]    = excl;
        excl += d;
    }
    if (t == 1023) g_rowptr[NN] = wsum[31];
}

__global__ void k_scatter(const int* __restrict__ src, const int* __restrict__ dst) {
    int e = blockIdx.x * blockDim.x + threadIdx.x;
    if (e < NE) {
        int p = atomicAdd(&g_pos[dst[e]], 1);
        g_esrc[p] = src[e];
    }
}

// ------------- warp-per-node mean aggregation (bf16 in/out) -----------------
template <int F>
__global__ __launch_bounds__(256) void k_agg(const __nv_bfloat16* __restrict__ hin,
                                             __nv_bfloat16* __restrict__ outp) {
    int warp = (blockIdx.x * blockDim.x + threadIdx.x) >> 5;
    if (warp >= NN) return;
    int lane = threadIdx.x & 31;
    int beg = g_rowptr[warp];
    int end = g_rowptr[warp + 1];
    constexpr int V = F / 32;          // bf16 per lane: 4 or 8
    float acc[V];
#pragma unroll
    for (int j = 0; j < V; ++j) acc[j] = 0.f;

    int e = beg;
    for (; e + 1 < end; e += 2) {
        int s0 = g_esrc[e], s1 = g_esrc[e + 1];
        const __nv_bfloat16* r0 = hin + (size_t)s0 * F + lane * V;
        const __nv_bfloat16* r1 = hin + (size_t)s1 * F + lane * V;
        if constexpr (V == 4) {
            uint2 u0 = __ldg((const uint2*)r0);
            uint2 u1 = __ldg((const uint2*)r1);
            float2 a0 = __bfloat1622float2(*(__nv_bfloat162*)&u0.x);
            float2 a1 = __bfloat1622float2(*(__nv_bfloat162*)&u0.y);
            float2 b0 = __bfloat1622float2(*(__nv_bfloat162*)&u1.x);
            float2 b1 = __bfloat1622float2(*(__nv_bfloat162*)&u1.y);
            acc[0] += a0.x + b0.x; acc[1] += a0.y + b0.y;
            acc[2] += a1.x + b1.x; acc[3] += a1.y + b1.y;
        } else {
            uint4 u0 = __ldg((const uint4*)r0);
            uint4 u1 = __ldg((const uint4*)r1);
            float2 p0 = __bfloat1622float2(*(__nv_bfloat162*)&u0.x);
            float2 p1 = __bfloat1622float2(*(__nv_bfloat162*)&u0.y);
            float2 p2 = __bfloat1622float2(*(__nv_bfloat162*)&u0.z);
            float2 p3 = __bfloat1622float2(*(__nv_bfloat162*)&u0.w);
            float2 q0 = __bfloat1622float2(*(__nv_bfloat162*)&u1.x);
            float2 q1 = __bfloat1622float2(*(__nv_bfloat162*)&u1.y);
            float2 q2 = __bfloat1622float2(*(__nv_bfloat162*)&u1.z);
            float2 q3 = __bfloat1622float2(*(__nv_bfloat162*)&u1.w);
            acc[0] += p0.x + q0.x; acc[1] += p0.y + q0.y;
            acc[2] += p1.x + q1.x; acc[3] += p1.y + q1.y;
            acc[4] += p2.x + q2.x; acc[5] += p2.y + q2.y;
            acc[6] += p3.x + q3.x; acc[7] += p3.y + q3.y;
        }
    }
    if (e < end) {
        const __nv_bfloat16* r0 = hin + (size_t)g_esrc[e] * F + lane * V;
        if constexpr (V == 4) {
            uint2 u0 = __ldg((const uint2*)r0);
            float2 a0 = __bfloat1622float2(*(__nv_bfloat162*)&u0.x);
            float2 a1 = __bfloat1622float2(*(__nv_bfloat162*)&u0.y);
            acc[0] += a0.x; acc[1] += a0.y; acc[2] += a1.x; acc[3] += a1.y;
        } else {
            uint4 u0 = __ldg((const uint4*)r0);
            float2 p0 = __bfloat1622float2(*(__nv_bfloat162*)&u0.x);
            float2 p1 = __bfloat1622float2(*(__nv_bfloat162*)&u0.y);
            float2 p2 = __bfloat1622float2(*(__nv_bfloat162*)&u0.z);
            float2 p3 = __bfloat1622float2(*(__nv_bfloat162*)&u0.w);
            acc[0] += p0.x; acc[1] += p0.y; acc[2] += p1.x; acc[3] += p1.y;
            acc[4] += p2.x; acc[5] += p2.y; acc[6] += p3.x; acc[7] += p3.y;
        }
    }
    float inv = (end > beg) ? (1.f / (float)(end - beg)) : 0.f;
    __nv_bfloat16 o[V];
#pragma unroll
    for (int j = 0; j < V; ++j) o[j] = __float2bfloat16(acc[j] * inv);
    if constexpr (V == 4)
        *(uint2*)(outp + (size_t)warp * F + lane * V) = *(uint2*)o;
    else
        *(uint4*)(outp + (size_t)warp * F + lane * V) = *(uint4*)o;
}

// ------- HMMA GEMM (cp.async 2-stage): C = relu(A @ B^T + bias) -------------
// A: [NN x K] bf16; B: [256 x K] bf16; C: [NN x 256] bf16
#define LDA      40                 // 32 + 8 pad (bf16); row stride 80 B
#define TILE_B   (128 * LDA * 2)    // 10240 bytes
#define STAGE_B  (2 * TILE_B)       // 20480 bytes: A, B
#define GEMM_SMEM (2 * STAGE_B)     // 40960 bytes

template <int K>
__global__ __launch_bounds__(256) void k_gemm_hmma(
    const __nv_bfloat16* __restrict__ A, const __nv_bfloat16* __restrict__ B,
    const float* __restrict__ bias, __nv_bfloat16* __restrict__ C)
{
    extern __shared__ char dsm[];
    const uint32_t sb0 = smem_u32(dsm);

    const int tid  = threadIdx.x;
    const int lane = tid & 31;
    const int wid  = tid >> 5;
    const int wm   = (wid >> 1) * 32;
    const int wn   = (wid & 1) * 64;
    const int m0   = blockIdx.x * 128;
    const int n0   = blockIdx.y * 128;

    float c[2][8][4];
#pragma unroll
    for (int i = 0; i < 2; ++i)
#pragma unroll
        for (int j = 0; j < 8; ++j)
#pragma unroll
            for (int q = 0; q < 4; ++q) c[i][j][q] = 0.f;

    const int aq = lane >> 3, ar = lane & 7;
    const int a_row = ar + (aq & 1) * 8;
    const int a_col = (aq >> 1) * 8;
    uint32_t aoff[2];
#pragma unroll
    for (int i = 0; i < 2; ++i)
        aoff[i] = (uint32_t)(((wm + i * 16 + a_row) * LDA + a_col) * 2);
    const int b_row = (aq >> 1) * 8 + ar;
    const int b_col = (aq & 1) * 8;
    uint32_t boff[4];
#pragma unroll
    for (int jp = 0; jp < 4; ++jp)
        boff[jp] = (uint32_t)(((wn + jp * 16 + b_row) * LDA + b_col) * 2);

    auto load_stage = [&](int k0, int s) {
        uint32_t base = sb0 + (uint32_t)s * STAGE_B;
#pragma unroll
        for (int t = 0; t < 2; ++t) {
            int idx = t * 256 + tid;          // 0..511
            int r = idx >> 2, cB = (idx & 3) * 8;
            uint32_t so = (uint32_t)((r * LDA + cB) * 2);
            int gr = m0 + r;
            bool ap = gr < NN;
            int grc = ap ? gr : (NN - 1);
            cp16(base + so, A + (size_t)grc * K + k0 + cB, ap);
            cp16(base + TILE_B + so, B + (size_t)(n0 + r) * K + k0 + cB, true);
        }
        cp_commit();
    };

    load_stage(0, 0);
    const int NCH = K / 32;
    for (int ch = 0; ch < NCH; ++ch) {
        if (ch + 1 < NCH) { load_stage((ch + 1) * 32, (ch + 1) & 1); cp_wait<1>(); }
        else              { cp_wait<0>(); }
        __syncthreads();
        uint32_t base = sb0 + (uint32_t)(ch & 1) * STAGE_B;
        uint32_t sa = base, sbm = base + TILE_B;
#pragma unroll
        for (int ks = 0; ks < 2; ++ks) {
            uint32_t af[2][4];
#pragma unroll
            for (int i = 0; i < 2; ++i) ldm_x4(af[i], sa + aoff[i] + ks * 32);
#pragma unroll
            for (int jp = 0; jp < 4; ++jp) {
                uint32_t bf[4];
                ldm_x4(bf, sbm + boff[jp] + ks * 32);
#pragma unroll
                for (int i = 0; i < 2; ++i) {
#pragma unroll
                    for (int jj = 0; jj < 2; ++jj)
                        mma16816(c[i][jp * 2 + jj], af[i], bf + jj * 2);
                }
            }
        }
        __syncthreads();
    }

    // epilogue: bias + relu, bf16 store
    const int g   = lane >> 2;
    const int tig = lane & 3;
#pragma unroll
    for (int i = 0; i < 2; ++i) {
#pragma unroll
        for (int j = 0; j < 8; ++j) {
            int col  = n0 + wn + j * 8 + 2 * tig;
            float b0 = bias[col], b1 = bias[col + 1];
            int r0 = m0 + wm + i * 16 + g;
            if (r0 < NN) {
                __nv_bfloat162 o = __floats2bfloat162_rn(
                    fmaxf(c[i][j][0] + b0, 0.f), fmaxf(c[i][j][1] + b1, 0.f));
                *(__nv_bfloat162*)(C + (size_t)r0 * 256 + col) = o;
            }
            int r1 = r0 + 8;
            if (r1 < NN) {
                __nv_bfloat162 o = __floats2bfloat162_rn(
                    fmaxf(c[i][j][2] + b0, 0.f), fmaxf(c[i][j][3] + b1, 0.f));
                *(__nv_bfloat162*)(C + (size_t)r1 * 256 + col) = o;
            }
        }
    }
}

// -------- fused per-graph readout + MLP (graph_ids sorted) ------------------
__global__ __launch_bounds__(256) void k_readout_mlp(
    const int* __restrict__ gids,
    const float* __restrict__ Wr1, const float* __restrict__ br1,
    const float* __restrict__ Wr2, const float* __restrict__ br2,
    float* __restrict__ out)
{
    int g = blockIdx.x;
    int f = threadIdx.x;                 // 256 threads
    __shared__ int sb_, se_;
    __shared__ float shg[DH];
    __shared__ float ws[4];
    if (f == 0) {
        int lo = 0, hi = NN;
        while (lo < hi) { int mid = (lo + hi) >> 1; if (gids[mid] < g) lo = mid + 1; else hi = mid; }
        sb_ = lo;
        lo = 0; hi = NN;
        while (lo < hi) { int mid = (lo + hi) >> 1; if (gids[mid] < g + 1) lo = mid + 1; else hi = mid; }
        se_ = lo;
    }
    __syncthreads();
    int beg = sb_, end = se_;
    float acc = 0.f;
    for (int n = beg; n < end; ++n)
        acc += __bfloat162float(g_h2[(size_t)n * DH + f]);
    shg[f] = acc / fmaxf((float)(end - beg), 1.f);
    __syncthreads();

    if (f < DH2) {
        float hac = br1[f];
#pragma unroll 4
        for (int k = 0; k < DH; ++k) hac += shg[k] * Wr1[k * DH2 + f];
        float v = hac * Wr2[f];
#pragma unroll
        for (int off = 16; off > 0; off >>= 1) v += __shfl_down_sync(0xffffffffu, v, off);
        if ((f & 31) == 0) ws[f >> 5] = v;
    }
    __syncthreads();
    if (f == 0) out[g] = ws[0] + ws[1] + ws[2] + ws[3] + br2[0];
}

// ---------------- launch ----------------------------------------------------
extern "C" void kernel_launch(void* const* d_in, const int* in_sizes, int n_in,
                              void* d_out, int out_size) {
    const float* h    = (const float*)d_in[0];
    const int*   src  = (const int*)  d_in[1];
    const int*   dst  = (const int*)  d_in[2];
    const int*   gids = (const int*)  d_in[3];
    const float* W1   = (const float*)d_in[4];
    const float* b1   = (const float*)d_in[5];
    const float* W2   = (const float*)d_in[6];
    const float* b2   = (const float*)d_in[7];
    const float* Wr1  = (const float*)d_in[8];
    const float* br1  = (const float*)d_in[9];
    const float* Wr2  = (const float*)d_in[10];
    const float* br2  = (const float*)d_in[11];
    float* out = (float*)d_out;

    __nv_bfloat16 *hb, *a, *h1, *h2, *w1, *w2;
    cudaGetSymbolAddress((void**)&hb, g_hb);
    cudaGetSymbolAddress((void**)&a,  g_a);
    cudaGetSymbolAddress((void**)&h1, g_h1);
    cudaGetSymbolAddress((void**)&h2, g_h2);
    cudaGetSymbolAddress((void**)&w1, g_w1);
    cudaGetSymbolAddress((void**)&w2, g_w2);

    cudaFuncSetAttribute(k_gemm_hmma<DIN>, cudaFuncAttributeMaxDynamicSharedMemorySize, GEMM_SMEM);
    cudaFuncSetAttribute(k_gemm_hmma<DH>,  cudaFuncAttributeMaxDynamicSharedMemorySize, GEMM_SMEM);

    const dim3 ggrid((NN + 127) / 128, 2);
    const int AGG_BLK = (NN * 32 + 255) / 256;   // warp per node

    // prep (h->bf16, W transposes, deg zero) + CSR build
    k_prep<<<(PREP_TOTAL + 255) / 256, 256>>>(h, W1, W2);
    k_hist<<<(NE + 255) / 256, 256>>>(dst);
    k_scan<<<1, 1024>>>();
    k_scatter<<<(NE + 255) / 256, 256>>>(src, dst);

    // layer 1
    k_agg<DIN><<<AGG_BLK, 256>>>(hb, a);
    k_gemm_hmma<DIN><<<ggrid, 256, GEMM_SMEM>>>(a, w1, b1, h1);

    // layer 2
    k_agg<DH><<<AGG_BLK, 256>>>(h1, a);
    k_gemm_hmma<DH><<<ggrid, 256, GEMM_SMEM>>>(a, w2, b2, h2);

    // fused readout + MLP
    k_readout_mlp<<<NG, 256>>>(gids, Wr1, br1, Wr2, br2, out);
}

// round 7
// speedup vs baseline: 2.3133x; 1.0032x over previous
#include <cuda_runtime.h>
#include <cuda_bf16.h>
#include <cstdint>

#define NN   50000
#define NE   800000
#define DIN  128
#define DH   256
#define NG   256
#define DH2  128

// ---------------- scratch (device globals; no allocations allowed) ----------
__device__ __nv_bfloat16 g_hb [(size_t)NN * DIN];  // input h, bf16
__device__ __nv_bfloat16 g_a  [(size_t)NN * DH];   // aggregated features, bf16
__device__ __nv_bfloat16 g_h1 [(size_t)NN * DH];   // layer-1 output, bf16
__device__ __nv_bfloat16 g_h2 [(size_t)NN * DH];   // layer-2 output, bf16
__device__ __nv_bfloat16 g_w1 [DH * DIN];          // W1^T bf16
__device__ __nv_bfloat16 g_w2 [DH * DH];           // W2^T bf16
__device__ int g_deg[NN];
__device__ int g_rowptr[NN + 1];
__device__ int g_pos[NN];
__device__ int g_esrc[NE];

// ---------------- helpers ---------------------------------------------------
__device__ __forceinline__ uint32_t smem_u32(const void* p) {
    uint32_t a;
    asm("{ .reg .u64 t; cvta.to.shared.u64 t, %1; cvt.u32.u64 %0, t; }"
        : "=r"(a) : "l"(p));
    return a;
}

__device__ __forceinline__ void ldm_x4(uint32_t* f, uint32_t sa) {
    asm volatile("ldmatrix.sync.aligned.m8n8.x4.shared.b16 {%0,%1,%2,%3}, [%4];"
                 : "=r"(f[0]), "=r"(f[1]), "=r"(f[2]), "=r"(f[3]) : "r"(sa));
}

__device__ __forceinline__ void mma16816(float* c, const uint32_t* a, const uint32_t* b) {
    asm volatile(
        "mma.sync.aligned.m16n8k16.row.col.f32.bf16.bf16.f32 "
        "{%0,%1,%2,%3}, {%4,%5,%6,%7}, {%8,%9}, {%0,%1,%2,%3};"
        : "+f"(c[0]), "+f"(c[1]), "+f"(c[2]), "+f"(c[3])
        : "r"(a[0]), "r"(a[1]), "r"(a[2]), "r"(a[3]), "r"(b[0]), "r"(b[1]));
}

__device__ __forceinline__ void cp16(uint32_t d, const void* s, bool p) {
    asm volatile("cp.async.cg.shared.global [%0], [%1], 16, %2;"
                 :: "r"(d), "l"(s), "r"(p ? 16 : 0));
}
__device__ __forceinline__ void cp_commit() { asm volatile("cp.async.commit_group;"); }
template <int N>
__device__ __forceinline__ void cp_wait() { asm volatile("cp.async.wait_group %0;" :: "n"(N)); }

__device__ __forceinline__ void acc_u2(float* acc, uint2 u) {
    float2 a = __bfloat1622float2(*(__nv_bfloat162*)&u.x);
    float2 b = __bfloat1622float2(*(__nv_bfloat162*)&u.y);
    acc[0] += a.x; acc[1] += a.y; acc[2] += b.x; acc[3] += b.y;
}
__device__ __forceinline__ void acc_u4(float* acc, uint4 u) {
    float2 a = __bfloat1622float2(*(__nv_bfloat162*)&u.x);
    float2 b = __bfloat1622float2(*(__nv_bfloat162*)&u.y);
    float2 c = __bfloat1622float2(*(__nv_bfloat162*)&u.z);
    float2 d = __bfloat1622float2(*(__nv_bfloat162*)&u.w);
    acc[0] += a.x; acc[1] += a.y; acc[2] += b.x; acc[3] += b.y;
    acc[4] += c.x; acc[5] += c.y; acc[6] += d.x; acc[7] += d.y;
}

// ---------------- fused prep: zero deg + h->bf16 + W1,W2 transpose ----------
#define PREP_H_ITEMS   (NN * DIN / 4)            // 1,600,000
#define PREP_W1_ITEMS  (DH * DIN)                // 32,768
#define PREP_W2_ITEMS  (DH * DH)                 // 65,536
#define PREP_TOTAL     (PREP_H_ITEMS + PREP_W1_ITEMS + PREP_W2_ITEMS + NN)

__global__ void k_prep(const float* __restrict__ h,
                       const float* __restrict__ W1,
                       const float* __restrict__ W2) {
    int i = blockIdx.x * blockDim.x + threadIdx.x;
    if (i < PREP_H_ITEMS) {
        float4 v = __ldg((const float4*)h + i);
        __nv_bfloat16 b[4] = { __float2bfloat16(v.x), __float2bfloat16(v.y),
                               __float2bfloat16(v.z), __float2bfloat16(v.w) };
        *(uint2*)(g_hb + 4 * (size_t)i) = *(uint2*)b;
        return;
    }
    i -= PREP_H_ITEMS;
    if (i < PREP_W1_ITEMS) {
        int n = i / DIN, k = i % DIN;
        g_w1[i] = __float2bfloat16(W1[(size_t)k * DH + n]);
        return;
    }
    i -= PREP_W1_ITEMS;
    if (i < PREP_W2_ITEMS) {
        int n = i / DH, k = i % DH;
        g_w2[i] = __float2bfloat16(W2[(size_t)k * DH + n]);
        return;
    }
    i -= PREP_W2_ITEMS;
    if (i < NN) g_deg[i] = 0;
}

// ---------------- CSR build -------------------------------------------------
__global__ void k_hist(const int* __restrict__ dst) {
    int e = blockIdx.x * blockDim.x + threadIdx.x;
    if (e < NE) atomicAdd(&g_deg[dst[e]], 1);
}

// chunked single-block scan: 1024 threads * 49 elems
__global__ void k_scan() {
    const int CH = 49;
    int t = threadIdx.x;
    int beg = t * CH;
    int end = beg + CH; if (end > NN) end = NN;
    int s = 0;
    for (int i = beg; i < end; ++i) s += g_deg[i];
    int lane = t & 31, w = t >> 5;
    int v = s;
#pragma unroll
    for (int o = 1; o < 32; o <<= 1) {
        int u = __shfl_up_sync(0xffffffffu, v, o);
        if (lane >= o) v += u;
    }
    __shared__ int wsum[32];
    if (lane == 31) wsum[w] = v;
    __syncthreads();
    if (w == 0) {
        int x = wsum[lane];
#pragma unroll
        for (int o = 1; o < 32; o <<= 1) {
            int u = __shfl_up_sync(0xffffffffu, x, o);
            if (lane >= o) x += u;
        }
        wsum[lane] = x;
    }
    __syncthreads();
    int excl = v - s + (w > 0 ? wsum[w - 1] : 0);
    for (int i = beg; i < end; ++i) {
        int d = g_deg[i];
        g_rowptr[i] = excl;
        g_pos[i]    = excl;
        excl += d;
    }
    if (t == 1023) g_rowptr[NN] = wsum[31];
}

__global__ void k_scatter(const int* __restrict__ src, const int* __restrict__ dst) {
    int e = blockIdx.x * blockDim.x + threadIdx.x;
    if (e < NE) {
        int p = atomicAdd(&g_pos[dst[e]], 1);
        g_esrc[p] = src[e];
    }
}

// ------------- warp-per-node mean aggregation, 4-edge unroll ----------------
template <int F>
__global__ __launch_bounds__(256) void k_agg(const __nv_bfloat16* __restrict__ hin,
                                             __nv_bfloat16* __restrict__ outp) {
    int warp = (blockIdx.x * blockDim.x + threadIdx.x) >> 5;
    if (warp >= NN) return;
    int lane = threadIdx.x & 31;
    int beg = g_rowptr[warp];
    int end = g_rowptr[warp + 1];
    constexpr int V = F / 32;          // bf16 per lane: 4 or 8
    float acc[V];
#pragma unroll
    for (int j = 0; j < V; ++j) acc[j] = 0.f;

    const size_t lo = (size_t)lane * V;
    int e = beg;
    for (; e + 3 < end; e += 4) {
        int s0 = g_esrc[e], s1 = g_esrc[e + 1], s2 = g_esrc[e + 2], s3 = g_esrc[e + 3];
        if constexpr (V == 4) {
            uint2 u0 = __ldg((const uint2*)(hin + (size_t)s0 * F + lo));
            uint2 u1 = __ldg((const uint2*)(hin + (size_t)s1 * F + lo));
            uint2 u2 = __ldg((const uint2*)(hin + (size_t)s2 * F + lo));
            uint2 u3 = __ldg((const uint2*)(hin + (size_t)s3 * F + lo));
            acc_u2(acc, u0); acc_u2(acc, u1); acc_u2(acc, u2); acc_u2(acc, u3);
        } else {
            uint4 u0 = __ldg((const uint4*)(hin + (size_t)s0 * F + lo));
            uint4 u1 = __ldg((const uint4*)(hin + (size_t)s1 * F + lo));
            uint4 u2 = __ldg((const uint4*)(hin + (size_t)s2 * F + lo));
            uint4 u3 = __ldg((const uint4*)(hin + (size_t)s3 * F + lo));
            acc_u4(acc, u0); acc_u4(acc, u1); acc_u4(acc, u2); acc_u4(acc, u3);
        }
    }
    for (; e < end; ++e) {
        int s0 = g_esrc[e];
        if constexpr (V == 4) {
            uint2 u0 = __ldg((const uint2*)(hin + (size_t)s0 * F + lo));
            acc_u2(acc, u0);
        } else {
            uint4 u0 = __ldg((const uint4*)(hin + (size_t)s0 * F + lo));
            acc_u4(acc, u0);
        }
    }
    float inv = (end > beg) ? (1.f / (float)(end - beg)) : 0.f;
    __nv_bfloat16 o[V];
#pragma unroll
    for (int j = 0; j < V; ++j) o[j] = __float2bfloat16(acc[j] * inv);
    if constexpr (V == 4)
        *(uint2*)(outp + (size_t)warp * F + lo) = *(uint2*)o;
    else
        *(uint4*)(outp + (size_t)warp * F + lo) = *(uint4*)o;
}

// ------- HMMA GEMM (cp.async 3-stage, 1 sync/iter): C = relu(A@B^T + b) ----
// A: [NN x K] bf16; B: [256 x K] bf16; C: [NN x 256] bf16
#define LDA      40                 // 32 + 8 pad (bf16); row stride 80 B
#define TILE_B   (128 * LDA * 2)    // 10240 bytes
#define STAGE_B  (2 * TILE_B)       // 20480 bytes: A, B
#define NSTAGE   3
#define GEMM_SMEM (NSTAGE * STAGE_B)  // 61440 bytes

template <int K>
__global__ __launch_bounds__(256) void k_gemm_hmma(
    const __nv_bfloat16* __restrict__ A, const __nv_bfloat16* __restrict__ B,
    const float* __restrict__ bias, __nv_bfloat16* __restrict__ C)
{
    extern __shared__ char dsm[];
    const uint32_t sb0 = smem_u32(dsm);

    const int tid  = threadIdx.x;
    const int lane = tid & 31;
    const int wid  = tid >> 5;
    const int wm   = (wid >> 1) * 32;
    const int wn   = (wid & 1) * 64;
    const int m0   = blockIdx.x * 128;
    const int n0   = blockIdx.y * 128;

    float c[2][8][4];
#pragma unroll
    for (int i = 0; i < 2; ++i)
#pragma unroll
        for (int j = 0; j < 8; ++j)
#pragma unroll
            for (int q = 0; q < 4; ++q) c[i][j][q] = 0.f;

    const int aq = lane >> 3, ar = lane & 7;
    const int a_row = ar + (aq & 1) * 8;
    const int a_col = (aq >> 1) * 8;
    uint32_t aoff[2];
#pragma unroll
    for (int i = 0; i < 2; ++i)
        aoff[i] = (uint32_t)(((wm + i * 16 + a_row) * LDA + a_col) * 2);
    const int b_row = (aq >> 1) * 8 + ar;
    const int b_col = (aq & 1) * 8;
    uint32_t boff[4];
#pragma unroll
    for (int jp = 0; jp < 4; ++jp)
        boff[jp] = (uint32_t)(((wn + jp * 16 + b_row) * LDA + b_col) * 2);

    auto load_stage = [&](int k0, int s) {
        uint32_t base = sb0 + (uint32_t)s * STAGE_B;
#pragma unroll
        for (int t = 0; t < 2; ++t) {
            int idx = t * 256 + tid;          // 0..511
            int r = idx >> 2, cB = (idx & 3) * 8;
            uint32_t so = (uint32_t)((r * LDA + cB) * 2);
            int gr = m0 + r;
            bool ap = gr < NN;
            int grc = ap ? gr : (NN - 1);
            cp16(base + so, A + (size_t)grc * K + k0 + cB, ap);
            cp16(base + TILE_B + so, B + (size_t)(n0 + r) * K + k0 + cB, true);
        }
        cp_commit();
    };

    const int NCH = K / 32;                  // 4 or 8 (>= 2)
    load_stage(0, 0);
    load_stage(32, 1);
    int st = 0;                              // stage of chunk ch
    for (int ch = 0; ch < NCH; ++ch) {
        if (ch + 1 < NCH) cp_wait<1>(); else cp_wait<0>();
        __syncthreads();
        if (ch + 2 < NCH) {
            int s2 = st + 2; if (s2 >= NSTAGE) s2 -= NSTAGE;
            load_stage((ch + 2) * 32, s2);
        }
        uint32_t base = sb0 + (uint32_t)st * STAGE_B;
        uint32_t sa = base, sbm = base + TILE_B;
#pragma unroll
        for (int ks = 0; ks < 2; ++ks) {
            uint32_t af[2][4];
#pragma unroll
            for (int i = 0; i < 2; ++i) ldm_x4(af[i], sa + aoff[i] + ks * 32);
#pragma unroll
            for (int jp = 0; jp < 4; ++jp) {
                uint32_t bf[4];
                ldm_x4(bf, sbm + boff[jp] + ks * 32);
#pragma unroll
                for (int i = 0; i < 2; ++i) {
#pragma unroll
                    for (int jj = 0; jj < 2; ++jj)
                        mma16816(c[i][jp * 2 + jj], af[i], bf + jj * 2);
                }
            }
        }
        if (++st == NSTAGE) st = 0;
    }

    // epilogue: bias + relu, bf16 store
    const int g   = lane >> 2;
    const int tig = lane & 3;
#pragma unroll
    for (int i = 0; i < 2; ++i) {
#pragma unroll
        for (int j = 0; j < 8; ++j) {
            int col  = n0 + wn + j * 8 + 2 * tig;
            float b0 = bias[col], b1 = bias[col + 1];
            int r0 = m0 + wm + i * 16 + g;
            if (r0 < NN) {
                __nv_bfloat162 o = __floats2bfloat162_rn(
                    fmaxf(c[i][j][0] + b0, 0.f), fmaxf(c[i][j][1] + b1, 0.f));
                *(__nv_bfloat162*)(C + (size_t)r0 * 256 + col) = o;
            }
            int r1 = r0 + 8;
            if (r1 < NN) {
                __nv_bfloat162 o = __floats2bfloat162_rn(
                    fmaxf(c[i][j][2] + b0, 0.f), fmaxf(c[i][j][3] + b1, 0.f));
                *(__nv_bfloat162*)(C + (size_t)r1 * 256 + col) = o;
            }
        }
    }
}

// -------- fused per-graph readout + MLP (graph_ids sorted) ------------------
__global__ __launch_bounds__(256) void k_readout_mlp(
    const int* __restrict__ gids,
    const float* __restrict__ Wr1, const float* __restrict__ br1,
    const float* __restrict__ Wr2, const float* __restrict__ br2,
    float* __restrict__ out)
{
    int g = blockIdx.x;
    int f = threadIdx.x;                 // 256 threads
    __shared__ int sb_, se_;
    __shared__ float shg[DH];
    __shared__ float ws[4];
    if (f == 0) {
        int lo = 0, hi = NN;
        while (lo < hi) { int mid = (lo + hi) >> 1; if (gids[mid] < g) lo = mid + 1; else hi = mid; }
        sb_ = lo;
        lo = 0; hi = NN;
        while (lo < hi) { int mid = (lo + hi) >> 1; if (gids[mid] < g + 1) lo = mid + 1; else hi = mid; }
        se_ = lo;
    }
    __syncthreads();
    int beg = sb_, end = se_;
    float acc = 0.f;
    for (int n = beg; n < end; ++n)
        acc += __bfloat162float(g_h2[(size_t)n * DH + f]);
    shg[f] = acc / fmaxf((float)(end - beg), 1.f);
    __syncthreads();

    if (f < DH2) {
        float hac = br1[f];
#pragma unroll 4
        for (int k = 0; k < DH; ++k) hac += shg[k] * Wr1[k * DH2 + f];
        float v = hac * Wr2[f];
#pragma unroll
        for (int off = 16; off > 0; off >>= 1) v += __shfl_down_sync(0xffffffffu, v, off);
        if ((f & 31) == 0) ws[f >> 5] = v;
    }
    __syncthreads();
    if (f == 0) out[g] = ws[0] + ws[1] + ws[2] + ws[3] + br2[0];
}

// ---------------- launch ----------------------------------------------------
extern "C" void kernel_launch(void* const* d_in, const int* in_sizes, int n_in,
                              void* d_out, int out_size) {
    const float* h    = (const float*)d_in[0];
    const int*   src  = (const int*)  d_in[1];
    const int*   dst  = (const int*)  d_in[2];
    const int*   gids = (const int*)  d_in[3];
    const float* W1   = (const float*)d_in[4];
    const float* b1   = (const float*)d_in[5];
    const float* W2   = (const float*)d_in[6];
    const float* b2   = (const float*)d_in[7];
    const float* Wr1  = (const float*)d_in[8];
    const float* br1  = (const float*)d_in[9];
    const float* Wr2  = (const float*)d_in[10];
    const float* br2  = (const float*)d_in[11];
    float* out = (float*)d_out;

    __nv_bfloat16 *hb, *a, *h1, *h2, *w1, *w2;
    cudaGetSymbolAddress((void**)&hb, g_hb);
    cudaGetSymbolAddress((void**)&a,  g_a);
    cudaGetSymbolAddress((void**)&h1, g_h1);
    cudaGetSymbolAddress((void**)&h2, g_h2);
    cudaGetSymbolAddress((void**)&w1, g_w1);
    cudaGetSymbolAddress((void**)&w2, g_w2);

    cudaFuncSetAttribute(k_gemm_hmma<DIN>, cudaFuncAttributeMaxDynamicSharedMemorySize, GEMM_SMEM);
    cudaFuncSetAttribute(k_gemm_hmma<DH>,  cudaFuncAttributeMaxDynamicSharedMemorySize, GEMM_SMEM);

    const dim3 ggrid((NN + 127) / 128, 2);
    const int AGG_BLK = (NN * 32 + 255) / 256;   // warp per node

    // prep (h->bf16, W transposes, deg zero) + CSR build
    k_prep<<<(PREP_TOTAL + 255) / 256, 256>>>(h, W1, W2);
    k_hist<<<(NE + 255) / 256, 256>>>(dst);
    k_scan<<<1, 1024>>>();
    k_scatter<<<(NE + 255) / 256, 256>>>(src, dst);

    // layer 1
    k_agg<DIN><<<AGG_BLK, 256>>>(hb, a);
    k_gemm_hmma<DIN><<<ggrid, 256, GEMM_SMEM>>>(a, w1, b1, h1);

    // layer 2
    k_agg<DH><<<AGG_BLK, 256>>>(h1, a);
    k_gemm_hmma<DH><<<ggrid, 256, GEMM_SMEM>>>(a, w2, b2, h2);

    // fused readout + MLP
    k_readout_mlp<<<NG, 256>>>(gids, Wr1, br1, Wr2, br2, out);
}